// round 12
// baseline (speedup 1.0000x reference)
#include <cuda_runtime.h>
#include <cuda_fp16.h>
#include <math.h>
#include <stdint.h>

#define S_LEN   2048
#define DIM     2048
#define NHEAD   16
#define HD      128
#define HIDDEN  5632
#define EPS     1e-6f

using fp16 = __half;

// ---------------------------------------------------------------------------
// Device scratch
// ---------------------------------------------------------------------------
__device__ float g_h  [S_LEN * DIM];

__device__ fp16 g_xn [S_LEN * DIM];
__device__ fp16 g_q  [S_LEN * DIM];
__device__ fp16 g_k  [S_LEN * DIM];
__device__ fp16 g_v16[S_LEN * DIM];
__device__ fp16 g_vT [NHEAD * HD * S_LEN];
__device__ fp16 g_at [S_LEN * DIM];
__device__ fp16 g_hn [S_LEN * DIM];
__device__ fp16 g_u1 [(size_t)S_LEN * HIDDEN];

__device__ fp16 g_wqT[DIM * DIM];
__device__ fp16 g_wkT[DIM * DIM];
__device__ fp16 g_wvT[DIM * DIM];
__device__ fp16 g_woT[DIM * DIM];
__device__ fp16 g_w1T[(size_t)HIDDEN * DIM];
__device__ fp16 g_w3T[(size_t)HIDDEN * DIM];
__device__ fp16 g_w2T[(size_t)DIM * HIDDEN];

// ---------------------------------------------------------------------------
// Helpers
// ---------------------------------------------------------------------------
__device__ __forceinline__ uint32_t smem_u32(const void* p) {
    uint32_t a;
    asm("{ .reg .u64 t; cvta.to.shared.u64 t, %1; cvt.u32.u64 %0, t; }" : "=r"(a) : "l"(p));
    return a;
}
__device__ __forceinline__ void cpa16(uint32_t d, const void* g) {
    asm volatile("cp.async.cg.shared.global [%0], [%1], 16;" :: "r"(d), "l"(g));
}
__device__ __forceinline__ void ldm_x4(uint32_t a, uint32_t (&f)[4]) {
    asm volatile("ldmatrix.sync.aligned.m8n8.x4.shared.b16 {%0,%1,%2,%3}, [%4];"
                 : "=r"(f[0]), "=r"(f[1]), "=r"(f[2]), "=r"(f[3]) : "r"(a));
}
__device__ __forceinline__ void mma16816(float (&c)[4], const uint32_t (&a)[4],
                                         uint32_t b0, uint32_t b1) {
    asm volatile("mma.sync.aligned.m16n8k16.row.col.f32.f16.f16.f32 "
                 "{%0,%1,%2,%3}, {%4,%5,%6,%7}, {%8,%9}, {%0,%1,%2,%3};"
                 : "+f"(c[0]), "+f"(c[1]), "+f"(c[2]), "+f"(c[3])
                 : "r"(a[0]), "r"(a[1]), "r"(a[2]), "r"(a[3]), "r"(b0), "r"(b1));
}
__device__ __forceinline__ uint32_t packh2(float lo, float hi) {
    uint32_t r;
    asm("cvt.rn.f16x2.f32 %0, %1, %2;" : "=r"(r) : "f"(hi), "f"(lo));
    return r;
}

// swizzled byte offset within a Rx32-fp16 tile (64B rows, 16B segs)
__device__ __forceinline__ uint32_t swz(int row, int seg) {
    return (uint32_t)(row * 64 + ((seg ^ ((row >> 1) & 3)) << 4));
}

// stage a 128x32 fp16 tile smem<-gmem via cp.async (256 threads, 2 ops/thread)
__device__ __forceinline__ void load_tile(const fp16* __restrict__ src, int ld,
                                          uint32_t dst, int tid) {
#pragma unroll
    for (int i = 0; i < 2; i++) {
        const int s = tid + i * 256;
        const int row = s >> 2, seg = s & 3;
        cpa16(dst + swz(row, seg), src + (size_t)row * ld + seg * 8);
    }
}
// stage a 64x32 fp16 tile (1 op/thread)
__device__ __forceinline__ void load_tile64(const fp16* __restrict__ src, int ld,
                                            uint32_t dst, int tid) {
    const int row = tid >> 2, seg = tid & 3;
    cpa16(dst + swz(row, seg), src + (size_t)row * ld + seg * 8);
}

// ---------------------------------------------------------------------------
// mma_gemm (dense GEMMs): C[M,N] = A[M,K] @ B[N,K]^T, fp16 in, fp32 accum.
// EPI: 1 fp32 + Dx residual; 3 rope fp16 out (q/k); 4 plain fp16 out (v)
// 128x128 tile, 8 warps (2x4), warp 64x32, K-chunk 32, 3-stage cp.async.
// ---------------------------------------------------------------------------
#define NSTAGE 3
#define GEMM_SMEM (NSTAGE * 16384)

template<int EPI>
__global__ __launch_bounds__(256)
void mma_gemm(const fp16* __restrict__ A_, int lda,
              const fp16* __restrict__ B_, int ldb,
              float* __restrict__ Cf, const float* __restrict__ Dx,
              fp16* __restrict__ Ch,
              const float* __restrict__ fc, const float* __restrict__ fs,
              int ldc, int K)
{
    const int m0 = blockIdx.y * 128, n0 = blockIdx.x * 128;
    const int nc = K >> 5;

    extern __shared__ char smem[];
    const uint32_t sb = smem_u32(smem);
    const int tid = threadIdx.x, wid = tid >> 5, lid = tid & 31;
    const int wm = wid >> 2, wn = wid & 3;

    const fp16* pA = A_ + (size_t)m0 * lda;
    const fp16* pB = B_ + (size_t)n0 * ldb;

    float acc[4][4][4];
#pragma unroll
    for (int i = 0; i < 4; i++)
#pragma unroll
        for (int j = 0; j < 4; j++)
#pragma unroll
            for (int t = 0; t < 4; t++) acc[i][j][t] = 0.f;

#pragma unroll
    for (int s = 0; s < NSTAGE - 1; s++) {
        if (s < nc) {
            const uint32_t base = sb + s * 16384;
            load_tile(pA + s * 32, lda, base,        tid);
            load_tile(pB + s * 32, ldb, base + 8192, tid);
        }
        asm volatile("cp.async.commit_group;" ::: "memory");
    }

    const int quad = lid >> 3, rr = lid & 7;

    for (int c = 0; c < nc; c++) {
        const int cp = c + NSTAGE - 1;
        if (cp < nc) {
            const uint32_t base = sb + (cp % NSTAGE) * 16384;
            load_tile(pA + cp * 32, lda, base,        tid);
            load_tile(pB + cp * 32, ldb, base + 8192, tid);
        }
        asm volatile("cp.async.commit_group;" ::: "memory");
        asm volatile("cp.async.wait_group %0;" :: "n"(NSTAGE - 1) : "memory");
        __syncthreads();

        const uint32_t base = sb + (c % NSTAGE) * 16384;
#pragma unroll
        for (int ks = 0; ks < 2; ks++) {
            uint32_t AF[4][4], BF[2][4];
#pragma unroll
            for (int mi = 0; mi < 4; mi++) {
                const int row = wm * 64 + mi * 16 + ((quad & 1) << 3) + rr;
                const int seg = ks * 2 + (quad >> 1);
                ldm_x4(base + swz(row, seg), AF[mi]);
            }
#pragma unroll
            for (int nj = 0; nj < 2; nj++) {
                const int row = wn * 32 + nj * 16 + ((quad >> 1) << 3) + rr;
                const int seg = ks * 2 + (quad & 1);
                ldm_x4(base + 8192 + swz(row, seg), BF[nj]);
            }
#pragma unroll
            for (int mi = 0; mi < 4; mi++)
#pragma unroll
                for (int nj = 0; nj < 2; nj++) {
                    mma16816(acc[mi][nj * 2],     AF[mi], BF[nj][0], BF[nj][1]);
                    mma16816(acc[mi][nj * 2 + 1], AF[mi], BF[nj][2], BF[nj][3]);
                }
        }
        __syncthreads();
    }

    const int gid = lid >> 2, tig = lid & 3;

#pragma unroll
    for (int mi = 0; mi < 4; mi++) {
#pragma unroll
        for (int k4 = 0; k4 < 4; k4++) {
            const int col = n0 + wn * 32 + k4 * 8 + tig * 2;
#pragma unroll
            for (int h2 = 0; h2 < 2; h2++) {
                const int row = m0 + wm * 64 + mi * 16 + gid + h2 * 8;
                float v0 = acc[mi][k4][h2 * 2 + 0];
                float v1 = acc[mi][k4][h2 * 2 + 1];
                if (EPI == 1) {
                    const size_t off = (size_t)row * ldc + col;
                    float2 d = *(const float2*)(Dx + off);
                    *(float2*)(Cf + off) = make_float2(v0 + d.x, v1 + d.y);
                } else if (EPI == 3) {
                    // rope: col pair (even, odd) within head (col % 128)
                    const int i = (col & 127) >> 1;
                    const float co = fc[row * 64 + i];
                    const float si = fs[row * 64 + i];
                    __half2 t;
                    t.x = __float2half(v0 * co - v1 * si);
                    t.y = __float2half(v0 * si + v1 * co);
                    *(__half2*)(Ch + (size_t)row * ldc + col) = t;
                } else {
                    __half2 t;
                    t.x = __float2half(v0); t.y = __float2half(v1);
                    *(__half2*)(Ch + (size_t)row * ldc + col) = t;
                }
            }
        }
    }
}

// ---------------------------------------------------------------------------
// ffn_gemm: u1 = silu(hn @ w1) * (hn @ w3), fp16 out.
// ---------------------------------------------------------------------------
__global__ __launch_bounds__(256)
void ffn_gemm(const fp16* __restrict__ A_, int lda,
              const fp16* __restrict__ B1_, const fp16* __restrict__ B3_, int ldb,
              fp16* __restrict__ U, int ldu, int K)
{
    const int m0 = blockIdx.y * 128, n0 = blockIdx.x * 64;
    const int nc = K >> 5;

    extern __shared__ char smem[];
    const uint32_t sb = smem_u32(smem);
    const int tid = threadIdx.x, wid = tid >> 5, lid = tid & 31;
    const int wm = wid >> 2, wn = wid & 3;

    const fp16* pA  = A_  + (size_t)m0 * lda;
    const fp16* pB1 = B1_ + (size_t)n0 * ldb;
    const fp16* pB3 = B3_ + (size_t)n0 * ldb;

    float acc[4][4][4];
#pragma unroll
    for (int i = 0; i < 4; i++)
#pragma unroll
        for (int j = 0; j < 4; j++)
#pragma unroll
            for (int t = 0; t < 4; t++) acc[i][j][t] = 0.f;

#pragma unroll
    for (int s = 0; s < NSTAGE - 1; s++) {
        if (s < nc) {
            const uint32_t base = sb + s * 16384;
            load_tile  (pA  + s * 32, lda, base,         tid);
            load_tile64(pB1 + s * 32, ldb, base + 8192,  tid);
            load_tile64(pB3 + s * 32, ldb, base + 12288, tid);
        }
        asm volatile("cp.async.commit_group;" ::: "memory");
    }

    const int quad = lid >> 3, rr = lid & 7;

    for (int c = 0; c < nc; c++) {
        const int cp = c + NSTAGE - 1;
        if (cp < nc) {
            const uint32_t base = sb + (cp % NSTAGE) * 16384;
            load_tile  (pA  + cp * 32, lda, base,         tid);
            load_tile64(pB1 + cp * 32, ldb, base + 8192,  tid);
            load_tile64(pB3 + cp * 32, ldb, base + 12288, tid);
        }
        asm volatile("cp.async.commit_group;" ::: "memory");
        asm volatile("cp.async.wait_group %0;" :: "n"(NSTAGE - 1) : "memory");
        __syncthreads();

        const uint32_t base = sb + (c % NSTAGE) * 16384;
        const uint32_t bB = base + ((wn < 2) ? 8192 : 12288);
#pragma unroll
        for (int ks = 0; ks < 2; ks++) {
            uint32_t AF[4][4], BF[2][4];
#pragma unroll
            for (int mi = 0; mi < 4; mi++) {
                const int row = wm * 64 + mi * 16 + ((quad & 1) << 3) + rr;
                const int seg = ks * 2 + (quad >> 1);
                ldm_x4(base + swz(row, seg), AF[mi]);
            }
#pragma unroll
            for (int nj = 0; nj < 2; nj++) {
                const int row = (wn & 1) * 32 + nj * 16 + ((quad >> 1) << 3) + rr;
                const int seg = ks * 2 + (quad & 1);
                ldm_x4(bB + swz(row, seg), BF[nj]);
            }
#pragma unroll
            for (int mi = 0; mi < 4; mi++)
#pragma unroll
                for (int nj = 0; nj < 2; nj++) {
                    mma16816(acc[mi][nj * 2],     AF[mi], BF[nj][0], BF[nj][1]);
                    mma16816(acc[mi][nj * 2 + 1], AF[mi], BF[nj][2], BF[nj][3]);
                }
        }
        __syncthreads();
    }

    float* stg = (float*)smem;    // 128 x 64 fp32 = 32KB
    const int gid = lid >> 2, tig = lid & 3;

    if (wn >= 2) {
#pragma unroll
        for (int mi = 0; mi < 4; mi++)
#pragma unroll
            for (int k4 = 0; k4 < 4; k4++) {
                const int col = (wn & 1) * 32 + k4 * 8 + tig * 2;
#pragma unroll
                for (int h2 = 0; h2 < 2; h2++) {
                    const int row = wm * 64 + mi * 16 + gid + h2 * 8;
                    *(float2*)(stg + row * 64 + col) =
                        make_float2(acc[mi][k4][h2 * 2], acc[mi][k4][h2 * 2 + 1]);
                }
            }
    }
    __syncthreads();
    if (wn < 2) {
#pragma unroll
        for (int mi = 0; mi < 4; mi++)
#pragma unroll
            for (int k4 = 0; k4 < 4; k4++) {
                const int col = (wn & 1) * 32 + k4 * 8 + tig * 2;
#pragma unroll
                for (int h2 = 0; h2 < 2; h2++) {
                    const int row = wm * 64 + mi * 16 + gid + h2 * 8;
                    float a0 = acc[mi][k4][h2 * 2], a1 = acc[mi][k4][h2 * 2 + 1];
                    float2 d = *(const float2*)(stg + row * 64 + col);
                    float u0 = a0 / (1.f + expf(-a0)) * d.x;
                    float u1v = a1 / (1.f + expf(-a1)) * d.y;
                    __half2 t;
                    t.x = __float2half(u0); t.y = __float2half(u1v);
                    *(__half2*)(U + (size_t)(m0 + row) * ldu + n0 + col) = t;
                }
            }
    }
}

// ---------------------------------------------------------------------------
// Flash attention (unchanged)
// ---------------------------------------------------------------------------
#define FL_SMEM (32768 + 65536 + 65536)

__global__ __launch_bounds__(256, 1)
void flash_kernel(const fp16* __restrict__ q, const fp16* __restrict__ k,
                  const fp16* __restrict__ vT, fp16* __restrict__ o)
{
    const int qt = 15 - blockIdx.x;
    const int z  = blockIdx.y;
    const int nkv = qt + 1;

    extern __shared__ char smem[];
    const uint32_t sQ = smem_u32(smem);
    const uint32_t sK = sQ + 32768;
    const uint32_t sV = sQ + 98304;

    const int tid = threadIdx.x, wid = tid >> 5, lid = tid & 31;
    const int gid = lid >> 2, tig = lid & 3;
    const int quad = lid >> 3, rr = lid & 7;

    const fp16* qbase = q + (size_t)(qt * 128) * DIM + z * HD;
    const fp16* kbase = k + z * HD;
    const fp16* vbase = vT + (size_t)z * HD * S_LEN;

#pragma unroll
    for (int j = 0; j < 4; j++) load_tile(qbase + j * 32, DIM, sQ + j * 8192, tid);
#pragma unroll
    for (int j = 0; j < 4; j++) load_tile(kbase + j * 32, DIM, sK + j * 8192, tid);
#pragma unroll
    for (int j = 0; j < 4; j++) load_tile(vbase + j * 32, S_LEN, sV + j * 8192, tid);
    asm volatile("cp.async.commit_group;" ::: "memory");

    float oacc[16][4];
#pragma unroll
    for (int t = 0; t < 16; t++)
#pragma unroll
        for (int j = 0; j < 4; j++) oacc[t][j] = 0.f;
    float m0 = -1e30f, m1 = -1e30f, l0 = 0.f, l1 = 0.f;
    const float sc2 = 0.08838834764831845f * 1.4426950408889634f;

    for (int c = 0; c < nkv; c++) {
        if (c + 1 < nkv) {
            const uint32_t bK = sK + ((c + 1) & 1) * 32768;
            const uint32_t bV = sV + ((c + 1) & 1) * 32768;
#pragma unroll
            for (int j = 0; j < 4; j++)
                load_tile(kbase + (size_t)((c + 1) * 128) * DIM + j * 32, DIM, bK + j * 8192, tid);
#pragma unroll
            for (int j = 0; j < 4; j++)
                load_tile(vbase + (c + 1) * 128 + j * 32, S_LEN, bV + j * 8192, tid);
        }
        asm volatile("cp.async.commit_group;" ::: "memory");
        asm volatile("cp.async.wait_group 1;" ::: "memory");
        __syncthreads();

        const uint32_t bK = sK + (c & 1) * 32768;
        const uint32_t bV = sV + (c & 1) * 32768;

        float sacc[16][4];
#pragma unroll
        for (int t = 0; t < 16; t++)
#pragma unroll
            for (int j = 0; j < 4; j++) sacc[t][j] = 0.f;

#pragma unroll
        for (int kc = 0; kc < 4; kc++) {
#pragma unroll
            for (int ks = 0; ks < 2; ks++) {
                uint32_t AF[4];
                {
                    const int row = wid * 16 + ((quad & 1) << 3) + rr;
                    const int seg = ks * 2 + (quad >> 1);
                    ldm_x4(sQ + kc * 8192 + swz(row, seg), AF);
                }
#pragma unroll
                for (int np = 0; np < 8; np++) {
                    uint32_t BF[4];
                    const int row = np * 16 + ((quad >> 1) << 3) + rr;
                    const int seg = ks * 2 + (quad & 1);
                    ldm_x4(bK + kc * 8192 + swz(row, seg), BF);
                    mma16816(sacc[np * 2],     AF, BF[0], BF[1]);
                    mma16816(sacc[np * 2 + 1], AF, BF[2], BF[3]);
                }
            }
        }

        if (c == qt) {
            const int r0 = wid * 16 + gid, r1 = r0 + 8;
#pragma unroll
            for (int t = 0; t < 16; t++) {
                const int col = t * 8 + tig * 2;
                if (col     > r0) sacc[t][0] = -1e30f;
                if (col + 1 > r0) sacc[t][1] = -1e30f;
                if (col     > r1) sacc[t][2] = -1e30f;
                if (col + 1 > r1) sacc[t][3] = -1e30f;
            }
        }

        float tm0 = -1e30f, tm1 = -1e30f;
#pragma unroll
        for (int t = 0; t < 16; t++) {
            tm0 = fmaxf(tm0, fmaxf(sacc[t][0], sacc[t][1]));
            tm1 = fmaxf(tm1, fmaxf(sacc[t][2], sacc[t][3]));
        }
        tm0 = fmaxf(tm0, __shfl_xor_sync(0xffffffffu, tm0, 1));
        tm0 = fmaxf(tm0, __shfl_xor_sync(0xffffffffu, tm0, 2));
        tm1 = fmaxf(tm1, __shfl_xor_sync(0xffffffffu, tm1, 1));
        tm1 = fmaxf(tm1, __shfl_xor_sync(0xffffffffu, tm1, 2));

        const float mn0 = fmaxf(m0, tm0), mn1 = fmaxf(m1, tm1);
        const float f0 = exp2f((m0 - mn0) * sc2);
        const float f1 = exp2f((m1 - mn1) * sc2);
        m0 = mn0; m1 = mn1;

        float rs0 = 0.f, rs1 = 0.f;
#pragma unroll
        for (int t = 0; t < 16; t++) {
            float p0 = exp2f((sacc[t][0] - mn0) * sc2);
            float p1 = exp2f((sacc[t][1] - mn0) * sc2);
            float p2 = exp2f((sacc[t][2] - mn1) * sc2);
            float p3 = exp2f((sacc[t][3] - mn1) * sc2);
            sacc[t][0] = p0; sacc[t][1] = p1; sacc[t][2] = p2; sacc[t][3] = p3;
            rs0 += p0 + p1; rs1 += p2 + p3;
        }
        rs0 += __shfl_xor_sync(0xffffffffu, rs0, 1);
        rs0 += __shfl_xor_sync(0xffffffffu, rs0, 2);
        rs1 += __shfl_xor_sync(0xffffffffu, rs1, 1);
        rs1 += __shfl_xor_sync(0xffffffffu, rs1, 2);
        l0 = l0 * f0 + rs0;
        l1 = l1 * f1 + rs1;

#pragma unroll
        for (int t = 0; t < 16; t++) {
            oacc[t][0] *= f0; oacc[t][1] *= f0;
            oacc[t][2] *= f1; oacc[t][3] *= f1;
        }

#pragma unroll
        for (int ks = 0; ks < 8; ks++) {
            uint32_t a[4];
            a[0] = packh2(sacc[2 * ks][0],     sacc[2 * ks][1]);
            a[1] = packh2(sacc[2 * ks][2],     sacc[2 * ks][3]);
            a[2] = packh2(sacc[2 * ks + 1][0], sacc[2 * ks + 1][1]);
            a[3] = packh2(sacc[2 * ks + 1][2], sacc[2 * ks + 1][3]);
            const int kc = ks >> 1, ksl = ks & 1;
#pragma unroll
            for (int np = 0; np < 8; np++) {
                uint32_t BF[4];
                const int row = np * 16 + ((quad >> 1) << 3) + rr;
                const int seg = ksl * 2 + (quad & 1);
                ldm_x4(bV + kc * 8192 + swz(row, seg), BF);
                mma16816(oacc[np * 2],     a, BF[0], BF[1]);
                mma16816(oacc[np * 2 + 1], a, BF[2], BF[3]);
            }
        }
        __syncthreads();
    }

    const float i0 = 1.f / l0, i1 = 1.f / l1;
    fp16* obase = o + (size_t)(qt * 128 + wid * 16) * DIM + z * HD;
#pragma unroll
    for (int t = 0; t < 16; t++) {
        const int col = t * 8 + tig * 2;
        __half2 w0, w1;
        w0.x = __float2half(oacc[t][0] * i0); w0.y = __float2half(oacc[t][1] * i0);
        w1.x = __float2half(oacc[t][2] * i1); w1.y = __float2half(oacc[t][3] * i1);
        *(__half2*)(obase + (size_t)gid * DIM + col)       = w0;
        *(__half2*)(obase + (size_t)(gid + 8) * DIM + col) = w1;
    }
}

// ---------------------------------------------------------------------------
// RMSNorm -> fp16
// ---------------------------------------------------------------------------
__global__ void rmsnorm_h_kernel(const float* __restrict__ x, const float* __restrict__ g,
                                 fp16* __restrict__ y) {
    const int row = blockIdx.x;
    const float* xr = x + (size_t)row * DIM;
    float ss = 0.f;
    for (int i = threadIdx.x; i < DIM / 4; i += 256) {
        float4 v = ((const float4*)xr)[i];
        ss += v.x * v.x + v.y * v.y + v.z * v.z + v.w * v.w;
    }
    __shared__ float red[8];
    __shared__ float rr_s;
#pragma unroll
    for (int o = 16; o; o >>= 1) ss += __shfl_xor_sync(0xffffffffu, ss, o);
    if ((threadIdx.x & 31) == 0) red[threadIdx.x >> 5] = ss;
    __syncthreads();
    if (threadIdx.x == 0) {
        float v = 0.f;
#pragma unroll
        for (int i = 0; i < 8; i++) v += red[i];
        rr_s = rsqrtf(v * (1.0f / DIM) + EPS);
    }
    __syncthreads();
    const float rr = rr_s;
    for (int i = threadIdx.x; i < DIM / 4; i += 256) {
        float4 v  = ((const float4*)xr)[i];
        float4 gg = ((const float4*)g)[i];
        __half2 a, b;
        a.x = __float2half(v.x * rr * gg.x);
        a.y = __float2half(v.y * rr * gg.y);
        b.x = __float2half(v.z * rr * gg.z);
        b.y = __float2half(v.w * rr * gg.w);
        const size_t o = (size_t)row * DIM + i * 4;
        *(__half2*)(y + o)     = a;
        *(__half2*)(y + o + 2) = b;
    }
}

// ---------------------------------------------------------------------------
// Weight transpose + convert (proven R9 version): W[K,N] -> WT[N,K] fp16.
// ---------------------------------------------------------------------------
__global__ void wconvT_kernel(const float* __restrict__ W, int K, int N,
                              fp16* __restrict__ T) {
    __shared__ float tb[64][65];
    const int n0 = blockIdx.x * 64, k0 = blockIdx.y * 64;
    const int tx = threadIdx.x, ty = threadIdx.y;   // (32, 8)
#pragma unroll
    for (int r = 0; r < 8; r++) {
        const int row = ty + 8 * r;
        float2 v = *(const float2*)(W + (size_t)(k0 + row) * N + n0 + tx * 2);
        tb[row][tx * 2]     = v.x;
        tb[row][tx * 2 + 1] = v.y;
    }
    __syncthreads();
#pragma unroll
    for (int r = 0; r < 8; r++) {
        const int n = ty + 8 * r;
        __half2 h;
        h.x = __float2half(tb[tx * 2][n]);
        h.y = __float2half(tb[tx * 2 + 1][n]);
        *(__half2*)(T + (size_t)(n0 + n) * K + k0 + tx * 2) = h;
    }
}

// ---------------------------------------------------------------------------
// V transpose per head (fp16 in): v16[S, DIM] -> vT[h][d][t]. 64x64, half2.
// ---------------------------------------------------------------------------
__global__ void vconvT16_kernel(const fp16* __restrict__ v16, fp16* __restrict__ T) {
    __shared__ fp16 tb[64][66];
    const int t0 = blockIdx.x * 64, d0 = blockIdx.y * 64, h = blockIdx.z;
    const int tx = threadIdx.x, ty = threadIdx.y;   // (32, 8)
#pragma unroll
    for (int r = 0; r < 8; r++) {
        const int row = ty + 8 * r;
        __half2 v = *(const __half2*)(v16 + (size_t)(t0 + row) * DIM + h * HD + d0 + tx * 2);
        tb[row][tx * 2]     = v.x;
        tb[row][tx * 2 + 1] = v.y;
    }
    __syncthreads();
#pragma unroll
    for (int r = 0; r < 8; r++) {
        const int d = ty + 8 * r;
        __half2 hh;
        hh.x = tb[tx * 2][d];
        hh.y = tb[tx * 2 + 1][d];
        *(__half2*)(T + ((size_t)h * HD + d0 + d) * S_LEN + t0 + tx * 2) = hh;
    }
}

// ---------------------------------------------------------------------------
// Orchestration: side-stream conversions; QKV GEMM split per weight so each
// gates only on its own conversion (pipelines conv against GEMM).
// ---------------------------------------------------------------------------
extern "C" void kernel_launch(void* const* d_in, const int* in_sizes, int n_in,
                              void* d_out, int out_size) {
    const float* x  = (const float*)d_in[0];
    const float* fc = (const float*)d_in[1];
    const float* fs = (const float*)d_in[2];
    const float* wq = (const float*)d_in[4];
    const float* wk = (const float*)d_in[5];
    const float* wv = (const float*)d_in[6];
    const float* wo = (const float*)d_in[7];
    const float* w1 = (const float*)d_in[8];
    const float* w2 = (const float*)d_in[9];
    const float* w3 = (const float*)d_in[10];
    const float* ga = (const float*)d_in[11];
    const float* gf = (const float*)d_in[12];
    float* out = (float*)d_out;

    cudaFuncSetAttribute(mma_gemm<1>, cudaFuncAttributeMaxDynamicSharedMemorySize, GEMM_SMEM);
    cudaFuncSetAttribute(mma_gemm<3>, cudaFuncAttributeMaxDynamicSharedMemorySize, GEMM_SMEM);
    cudaFuncSetAttribute(mma_gemm<4>, cudaFuncAttributeMaxDynamicSharedMemorySize, GEMM_SMEM);
    cudaFuncSetAttribute(ffn_gemm,    cudaFuncAttributeMaxDynamicSharedMemorySize, GEMM_SMEM);
    cudaFuncSetAttribute(flash_kernel, cudaFuncAttributeMaxDynamicSharedMemorySize, FL_SMEM);

    float *h;
    fp16 *xn, *q, *k, *v16, *vT, *at, *hn, *u1;
    fp16 *wqT, *wkT, *wvT, *woT, *w1T, *w2T, *w3T;
    cudaGetSymbolAddress((void**)&h,    g_h);
    cudaGetSymbolAddress((void**)&xn,   g_xn);
    cudaGetSymbolAddress((void**)&q,    g_q);
    cudaGetSymbolAddress((void**)&k,    g_k);
    cudaGetSymbolAddress((void**)&v16,  g_v16);
    cudaGetSymbolAddress((void**)&vT,   g_vT);
    cudaGetSymbolAddress((void**)&at,   g_at);
    cudaGetSymbolAddress((void**)&hn,   g_hn);
    cudaGetSymbolAddress((void**)&u1,   g_u1);
    cudaGetSymbolAddress((void**)&wqT,  g_wqT);
    cudaGetSymbolAddress((void**)&wkT,  g_wkT);
    cudaGetSymbolAddress((void**)&wvT,  g_wvT);
    cudaGetSymbolAddress((void**)&woT,  g_woT);
    cudaGetSymbolAddress((void**)&w1T,  g_w1T);
    cudaGetSymbolAddress((void**)&w2T,  g_w2T);
    cudaGetSymbolAddress((void**)&w3T,  g_w3T);

    // one-time host-side stream/event objects (no device memory involved)
    static cudaStream_t s1 = []() {
        cudaStream_t s; cudaStreamCreateWithFlags(&s, cudaStreamNonBlocking); return s;
    }();
    static cudaEvent_t eFork = []() {
        cudaEvent_t e; cudaEventCreateWithFlags(&e, cudaEventDisableTiming); return e;
    }();
    static cudaEvent_t eWq = []() {
        cudaEvent_t e; cudaEventCreateWithFlags(&e, cudaEventDisableTiming); return e;
    }();
    static cudaEvent_t eWk = []() {
        cudaEvent_t e; cudaEventCreateWithFlags(&e, cudaEventDisableTiming); return e;
    }();
    static cudaEvent_t eWv = []() {
        cudaEvent_t e; cudaEventCreateWithFlags(&e, cudaEventDisableTiming); return e;
    }();
    static cudaEvent_t eWO = []() {
        cudaEvent_t e; cudaEventCreateWithFlags(&e, cudaEventDisableTiming); return e;
    }();
    static cudaEvent_t eFFN = []() {
        cudaEvent_t e; cudaEventCreateWithFlags(&e, cudaEventDisableTiming); return e;
    }();
    static cudaEvent_t eW2 = []() {
        cudaEvent_t e; cudaEventCreateWithFlags(&e, cudaEventDisableTiming); return e;
    }();

    const dim3 tb32(32, 8);
    const dim3 g16(16, 16);

    // fork the side stream off the main (capture) stream
    cudaEventRecord(eFork, 0);
    cudaStreamWaitEvent(s1, eFork, 0);

    // ---- side stream: weight conversions, one event each for QKV pipelining ----
    wconvT_kernel<<<dim3(32, 32), tb32, 0, s1>>>(wq, DIM, DIM, wqT);
    cudaEventRecord(eWq, s1);
    wconvT_kernel<<<dim3(32, 32), tb32, 0, s1>>>(wk, DIM, DIM, wkT);
    cudaEventRecord(eWk, s1);
    wconvT_kernel<<<dim3(32, 32), tb32, 0, s1>>>(wv, DIM, DIM, wvT);
    cudaEventRecord(eWv, s1);
    wconvT_kernel<<<dim3(32, 32), tb32, 0, s1>>>(wo, DIM, DIM, woT);
    cudaEventRecord(eWO, s1);
    wconvT_kernel<<<dim3(88, 32), tb32, 0, s1>>>(w1, DIM, HIDDEN, w1T);
    wconvT_kernel<<<dim3(88, 32), tb32, 0, s1>>>(w3, DIM, HIDDEN, w3T);
    cudaEventRecord(eFFN, s1);
    wconvT_kernel<<<dim3(32, 88), tb32, 0, s1>>>(w2, HIDDEN, DIM, w2T);
    cudaEventRecord(eW2, s1);

    // ---- main stream: compute chain ----
    rmsnorm_h_kernel<<<S_LEN, 256>>>(x, ga, xn);

    // Q/K GEMMs with rope epilogue; V GEMM plain fp16 — each gated on its conv
    cudaStreamWaitEvent(0, eWq, 0);
    mma_gemm<3><<<g16, 256, GEMM_SMEM>>>(xn, DIM, wqT, DIM,
        nullptr, nullptr, q, fc, fs, DIM, DIM);
    cudaStreamWaitEvent(0, eWk, 0);
    mma_gemm<3><<<g16, 256, GEMM_SMEM>>>(xn, DIM, wkT, DIM,
        nullptr, nullptr, k, fc, fs, DIM, DIM);
    cudaStreamWaitEvent(0, eWv, 0);
    mma_gemm<4><<<g16, 256, GEMM_SMEM>>>(xn, DIM, wvT, DIM,
        nullptr, nullptr, v16, nullptr, nullptr, DIM, DIM);

    // V transpose per head
    vconvT16_kernel<<<dim3(32, 2, NHEAD), tb32>>>(v16, vT);

    // flash attention
    flash_kernel<<<dim3(16, NHEAD), 256, FL_SMEM>>>(q, k, vT, at);

    // h = x + attn @ wo (needs woT)
    cudaStreamWaitEvent(0, eWO, 0);
    mma_gemm<1><<<g16, 256, GEMM_SMEM>>>(at, DIM, woT, DIM,
        h, x, nullptr, nullptr, nullptr, DIM, DIM);

    // hn = rmsnorm(h) fp16
    rmsnorm_h_kernel<<<S_LEN, 256>>>(h, gf, hn);

    // fused FFN (needs w1T, w3T)
    cudaStreamWaitEvent(0, eFFN, 0);
    ffn_gemm<<<dim3(HIDDEN / 64, 16), 256, GEMM_SMEM>>>(hn, DIM, w1T, w3T, DIM,
        u1, HIDDEN, DIM);

    // out = h + u1 @ w2 (needs w2T; also joins the side branch back)
    cudaStreamWaitEvent(0, eW2, 0);
    mma_gemm<1><<<g16, 256, GEMM_SMEM>>>(u1, HIDDEN, w2T, HIDDEN,
        out, h, nullptr, nullptr, nullptr, DIM, HIDDEN);
}

// round 14
// speedup vs baseline: 1.0168x; 1.0168x over previous
#include <cuda_runtime.h>
#include <cuda_fp16.h>
#include <math.h>
#include <stdint.h>

#define S_LEN   2048
#define DIM     2048
#define NHEAD   16
#define HD      128
#define HIDDEN  5632
#define EPS     1e-6f
#define QKV_N   (3 * DIM)     // 6144

using fp16 = __half;

// ---------------------------------------------------------------------------
// Device scratch
// ---------------------------------------------------------------------------
__device__ float g_h  [S_LEN * DIM];

__device__ fp16 g_xn [S_LEN * DIM];
__device__ fp16 g_q  [S_LEN * DIM];
__device__ fp16 g_k  [S_LEN * DIM];
__device__ fp16 g_vT [NHEAD * HD * S_LEN];
__device__ fp16 g_at [S_LEN * DIM];
__device__ fp16 g_hn [S_LEN * DIM];
__device__ fp16 g_u1 [(size_t)S_LEN * HIDDEN];

__device__ fp16 g_wqkvT[(size_t)QKV_N * DIM];              // [6144, 2048]
__device__ fp16 g_woT[DIM * DIM];
__device__ fp16 g_w1T[(size_t)HIDDEN * DIM];
__device__ fp16 g_w3T[(size_t)HIDDEN * DIM];
__device__ fp16 g_w2T[(size_t)DIM * HIDDEN];

// ---------------------------------------------------------------------------
// Helpers
// ---------------------------------------------------------------------------
__device__ __forceinline__ uint32_t smem_u32(const void* p) {
    uint32_t a;
    asm("{ .reg .u64 t; cvta.to.shared.u64 t, %1; cvt.u32.u64 %0, t; }" : "=r"(a) : "l"(p));
    return a;
}
__device__ __forceinline__ void cpa16(uint32_t d, const void* g) {
    asm volatile("cp.async.cg.shared.global [%0], [%1], 16;" :: "r"(d), "l"(g));
}
__device__ __forceinline__ void ldm_x4(uint32_t a, uint32_t (&f)[4]) {
    asm volatile("ldmatrix.sync.aligned.m8n8.x4.shared.b16 {%0,%1,%2,%3}, [%4];"
                 : "=r"(f[0]), "=r"(f[1]), "=r"(f[2]), "=r"(f[3]) : "r"(a));
}
__device__ __forceinline__ void mma16816(float (&c)[4], const uint32_t (&a)[4],
                                         uint32_t b0, uint32_t b1) {
    asm volatile("mma.sync.aligned.m16n8k16.row.col.f32.f16.f16.f32 "
                 "{%0,%1,%2,%3}, {%4,%5,%6,%7}, {%8,%9}, {%0,%1,%2,%3};"
                 : "+f"(c[0]), "+f"(c[1]), "+f"(c[2]), "+f"(c[3])
                 : "r"(a[0]), "r"(a[1]), "r"(a[2]), "r"(a[3]), "r"(b0), "r"(b1));
}
__device__ __forceinline__ uint32_t packh2(float lo, float hi) {
    uint32_t r;
    asm("cvt.rn.f16x2.f32 %0, %1, %2;" : "=r"(r) : "f"(hi), "f"(lo));
    return r;
}

// swizzled byte offset within a Rx32-fp16 tile (64B rows, 16B segs)
__device__ __forceinline__ uint32_t swz(int row, int seg) {
    return (uint32_t)(row * 64 + ((seg ^ ((row >> 1) & 3)) << 4));
}

// stage a 128x32 fp16 tile smem<-gmem via cp.async (256 threads, 2 ops/thread)
__device__ __forceinline__ void load_tile(const fp16* __restrict__ src, int ld,
                                          uint32_t dst, int tid) {
#pragma unroll
    for (int i = 0; i < 2; i++) {
        const int s = tid + i * 256;
        const int row = s >> 2, seg = s & 3;
        cpa16(dst + swz(row, seg), src + (size_t)row * ld + seg * 8);
    }
}
// stage a 64x32 fp16 tile (1 op/thread)
__device__ __forceinline__ void load_tile64(const fp16* __restrict__ src, int ld,
                                            uint32_t dst, int tid) {
    const int row = tid >> 2, seg = tid & 3;
    cpa16(dst + swz(row, seg), src + (size_t)row * ld + seg * 8);
}

// ---------------------------------------------------------------------------
// mma_gemm (dense GEMMs): C[M,N] = A[M,K] @ B[N,K]^T, fp16 in, fp32 accum.
// EPI: 1 fp32 + Dx residual; 3 QKV mode (rope q/k fp16 + V direct-transposed)
// 128x128 tile, 8 warps (2x4), warp 64x32, K-chunk 32, 3-stage cp.async.
// ---------------------------------------------------------------------------
#define NSTAGE 3
#define GEMM_SMEM (NSTAGE * 16384)

template<int EPI>
__global__ __launch_bounds__(256)
void mma_gemm(const fp16* __restrict__ A_, int lda,
              const fp16* __restrict__ B_, int ldb,
              float* __restrict__ Cf, const float* __restrict__ Dx,
              fp16* __restrict__ Cq, fp16* __restrict__ Ck, fp16* __restrict__ CvT,
              const float* __restrict__ fc, const float* __restrict__ fs,
              int ldc, int K)
{
    const int m0 = blockIdx.y * 128, n0 = blockIdx.x * 128;
    const int nc = K >> 5;

    extern __shared__ char smem[];
    const uint32_t sb = smem_u32(smem);
    const int tid = threadIdx.x, wid = tid >> 5, lid = tid & 31;
    const int wm = wid >> 2, wn = wid & 3;

    const fp16* pA = A_ + (size_t)m0 * lda;
    const fp16* pB = B_ + (size_t)n0 * ldb;

    float acc[4][4][4];
#pragma unroll
    for (int i = 0; i < 4; i++)
#pragma unroll
        for (int j = 0; j < 4; j++)
#pragma unroll
            for (int t = 0; t < 4; t++) acc[i][j][t] = 0.f;

#pragma unroll
    for (int s = 0; s < NSTAGE - 1; s++) {
        if (s < nc) {
            const uint32_t base = sb + s * 16384;
            load_tile(pA + s * 32, lda, base,        tid);
            load_tile(pB + s * 32, ldb, base + 8192, tid);
        }
        asm volatile("cp.async.commit_group;" ::: "memory");
    }

    const int quad = lid >> 3, rr = lid & 7;

    for (int c = 0; c < nc; c++) {
        const int cp = c + NSTAGE - 1;
        if (cp < nc) {
            const uint32_t base = sb + (cp % NSTAGE) * 16384;
            load_tile(pA + cp * 32, lda, base,        tid);
            load_tile(pB + cp * 32, ldb, base + 8192, tid);
        }
        asm volatile("cp.async.commit_group;" ::: "memory");
        asm volatile("cp.async.wait_group %0;" :: "n"(NSTAGE - 1) : "memory");
        __syncthreads();

        const uint32_t base = sb + (c % NSTAGE) * 16384;
#pragma unroll
        for (int ks = 0; ks < 2; ks++) {
            uint32_t AF[4][4], BF[2][4];
#pragma unroll
            for (int mi = 0; mi < 4; mi++) {
                const int row = wm * 64 + mi * 16 + ((quad & 1) << 3) + rr;
                const int seg = ks * 2 + (quad >> 1);
                ldm_x4(base + swz(row, seg), AF[mi]);
            }
#pragma unroll
            for (int nj = 0; nj < 2; nj++) {
                const int row = wn * 32 + nj * 16 + ((quad >> 1) << 3) + rr;
                const int seg = ks * 2 + (quad & 1);
                ldm_x4(base + 8192 + swz(row, seg), BF[nj]);
            }
#pragma unroll
            for (int mi = 0; mi < 4; mi++)
#pragma unroll
                for (int nj = 0; nj < 2; nj++) {
                    mma16816(acc[mi][nj * 2],     AF[mi], BF[nj][0], BF[nj][1]);
                    mma16816(acc[mi][nj * 2 + 1], AF[mi], BF[nj][2], BF[nj][3]);
                }
        }
        __syncthreads();
    }

    const int gid = lid >> 2, tig = lid & 3;

#pragma unroll
    for (int mi = 0; mi < 4; mi++) {
#pragma unroll
        for (int k4 = 0; k4 < 4; k4++) {
            const int col = n0 + wn * 32 + k4 * 8 + tig * 2;
#pragma unroll
            for (int h2 = 0; h2 < 2; h2++) {
                const int row = m0 + wm * 64 + mi * 16 + gid + h2 * 8;
                float v0 = acc[mi][k4][h2 * 2 + 0];
                float v1 = acc[mi][k4][h2 * 2 + 1];
                if (EPI == 1) {
                    const size_t off = (size_t)row * ldc + col;
                    float2 d = *(const float2*)(Dx + off);
                    *(float2*)(Cf + off) = make_float2(v0 + d.x, v1 + d.y);
                } else {
                    // EPI == 3: QKV mode. col in [0, 6144).
                    if (col < 4096) {
                        const int i = (col & 127) >> 1;
                        const float co = fc[row * 64 + i];
                        const float si = fs[row * 64 + i];
                        const float r_ = v0 * co - v1 * si;
                        const float i_ = v0 * si + v1 * co;
                        fp16* dst = (col < 2048) ? Cq : Ck;
                        __half2 t;
                        t.x = __float2half(r_); t.y = __float2half(i_);
                        *(__half2*)(dst + (size_t)row * DIM + (col & 2047)) = t;
                    } else {
                        // V: write directly transposed vT[h][d][t]
                        const int c2 = col - 4096;     // head h = c2>>7, d = c2&127
                        fp16* dst = CvT + (size_t)c2 * S_LEN + row;
                        dst[0]     = __float2half(v0);
                        dst[S_LEN] = __float2half(v1);
                    }
                }
            }
        }
    }
}

// ---------------------------------------------------------------------------
// ffn_gemm: u1 = silu(hn @ w1) * (hn @ w3), fp16 out.
// ---------------------------------------------------------------------------
__global__ __launch_bounds__(256)
void ffn_gemm(const fp16* __restrict__ A_, int lda,
              const fp16* __restrict__ B1_, const fp16* __restrict__ B3_, int ldb,
              fp16* __restrict__ U, int ldu, int K)
{
    const int m0 = blockIdx.y * 128, n0 = blockIdx.x * 64;
    const int nc = K >> 5;

    extern __shared__ char smem[];
    const uint32_t sb = smem_u32(smem);
    const int tid = threadIdx.x, wid = tid >> 5, lid = tid & 31;
    const int wm = wid >> 2, wn = wid & 3;

    const fp16* pA  = A_  + (size_t)m0 * lda;
    const fp16* pB1 = B1_ + (size_t)n0 * ldb;
    const fp16* pB3 = B3_ + (size_t)n0 * ldb;

    float acc[4][4][4];
#pragma unroll
    for (int i = 0; i < 4; i++)
#pragma unroll
        for (int j = 0; j < 4; j++)
#pragma unroll
            for (int t = 0; t < 4; t++) acc[i][j][t] = 0.f;

#pragma unroll
    for (int s = 0; s < NSTAGE - 1; s++) {
        if (s < nc) {
            const uint32_t base = sb + s * 16384;
            load_tile  (pA  + s * 32, lda, base,         tid);
            load_tile64(pB1 + s * 32, ldb, base + 8192,  tid);
            load_tile64(pB3 + s * 32, ldb, base + 12288, tid);
        }
        asm volatile("cp.async.commit_group;" ::: "memory");
    }

    const int quad = lid >> 3, rr = lid & 7;

    for (int c = 0; c < nc; c++) {
        const int cp = c + NSTAGE - 1;
        if (cp < nc) {
            const uint32_t base = sb + (cp % NSTAGE) * 16384;
            load_tile  (pA  + cp * 32, lda, base,         tid);
            load_tile64(pB1 + cp * 32, ldb, base + 8192,  tid);
            load_tile64(pB3 + cp * 32, ldb, base + 12288, tid);
        }
        asm volatile("cp.async.commit_group;" ::: "memory");
        asm volatile("cp.async.wait_group %0;" :: "n"(NSTAGE - 1) : "memory");
        __syncthreads();

        const uint32_t base = sb + (c % NSTAGE) * 16384;
        const uint32_t bB = base + ((wn < 2) ? 8192 : 12288);
#pragma unroll
        for (int ks = 0; ks < 2; ks++) {
            uint32_t AF[4][4], BF[2][4];
#pragma unroll
            for (int mi = 0; mi < 4; mi++) {
                const int row = wm * 64 + mi * 16 + ((quad & 1) << 3) + rr;
                const int seg = ks * 2 + (quad >> 1);
                ldm_x4(base + swz(row, seg), AF[mi]);
            }
#pragma unroll
            for (int nj = 0; nj < 2; nj++) {
                const int row = (wn & 1) * 32 + nj * 16 + ((quad >> 1) << 3) + rr;
                const int seg = ks * 2 + (quad & 1);
                ldm_x4(bB + swz(row, seg), BF[nj]);
            }
#pragma unroll
            for (int mi = 0; mi < 4; mi++)
#pragma unroll
                for (int nj = 0; nj < 2; nj++) {
                    mma16816(acc[mi][nj * 2],     AF[mi], BF[nj][0], BF[nj][1]);
                    mma16816(acc[mi][nj * 2 + 1], AF[mi], BF[nj][2], BF[nj][3]);
                }
        }
        __syncthreads();
    }

    float* stg = (float*)smem;    // 128 x 64 fp32 = 32KB
    const int gid = lid >> 2, tig = lid & 3;

    if (wn >= 2) {
#pragma unroll
        for (int mi = 0; mi < 4; mi++)
#pragma unroll
            for (int k4 = 0; k4 < 4; k4++) {
                const int col = (wn & 1) * 32 + k4 * 8 + tig * 2;
#pragma unroll
                for (int h2 = 0; h2 < 2; h2++) {
                    const int row = wm * 64 + mi * 16 + gid + h2 * 8;
                    *(float2*)(stg + row * 64 + col) =
                        make_float2(acc[mi][k4][h2 * 2], acc[mi][k4][h2 * 2 + 1]);
                }
            }
    }
    __syncthreads();
    if (wn < 2) {
#pragma unroll
        for (int mi = 0; mi < 4; mi++)
#pragma unroll
            for (int k4 = 0; k4 < 4; k4++) {
                const int col = (wn & 1) * 32 + k4 * 8 + tig * 2;
#pragma unroll
                for (int h2 = 0; h2 < 2; h2++) {
                    const int row = wm * 64 + mi * 16 + gid + h2 * 8;
                    float a0 = acc[mi][k4][h2 * 2], a1 = acc[mi][k4][h2 * 2 + 1];
                    float2 d = *(const float2*)(stg + row * 64 + col);
                    float u0 = a0 / (1.f + expf(-a0)) * d.x;
                    float u1v = a1 / (1.f + expf(-a1)) * d.y;
                    __half2 t;
                    t.x = __float2half(u0); t.y = __float2half(u1v);
                    *(__half2*)(U + (size_t)(m0 + row) * ldu + n0 + col) = t;
                }
            }
    }
}

// ---------------------------------------------------------------------------
// Flash attention (unchanged)
// ---------------------------------------------------------------------------
#define FL_SMEM (32768 + 65536 + 65536)

__global__ __launch_bounds__(256, 1)
void flash_kernel(const fp16* __restrict__ q, const fp16* __restrict__ k,
                  const fp16* __restrict__ vT, fp16* __restrict__ o)
{
    const int qt = 15 - blockIdx.x;
    const int z  = blockIdx.y;
    const int nkv = qt + 1;

    extern __shared__ char smem[];
    const uint32_t sQ = smem_u32(smem);
    const uint32_t sK = sQ + 32768;
    const uint32_t sV = sQ + 98304;

    const int tid = threadIdx.x, wid = tid >> 5, lid = tid & 31;
    const int gid = lid >> 2, tig = lid & 3;
    const int quad = lid >> 3, rr = lid & 7;

    const fp16* qbase = q + (size_t)(qt * 128) * DIM + z * HD;
    const fp16* kbase = k + z * HD;
    const fp16* vbase = vT + (size_t)z * HD * S_LEN;

#pragma unroll
    for (int j = 0; j < 4; j++) load_tile(qbase + j * 32, DIM, sQ + j * 8192, tid);
#pragma unroll
    for (int j = 0; j < 4; j++) load_tile(kbase + j * 32, DIM, sK + j * 8192, tid);
#pragma unroll
    for (int j = 0; j < 4; j++) load_tile(vbase + j * 32, S_LEN, sV + j * 8192, tid);
    asm volatile("cp.async.commit_group;" ::: "memory");

    float oacc[16][4];
#pragma unroll
    for (int t = 0; t < 16; t++)
#pragma unroll
        for (int j = 0; j < 4; j++) oacc[t][j] = 0.f;
    float m0 = -1e30f, m1 = -1e30f, l0 = 0.f, l1 = 0.f;
    const float sc2 = 0.08838834764831845f * 1.4426950408889634f;

    for (int c = 0; c < nkv; c++) {
        if (c + 1 < nkv) {
            const uint32_t bK = sK + ((c + 1) & 1) * 32768;
            const uint32_t bV = sV + ((c + 1) & 1) * 32768;
#pragma unroll
            for (int j = 0; j < 4; j++)
                load_tile(kbase + (size_t)((c + 1) * 128) * DIM + j * 32, DIM, bK + j * 8192, tid);
#pragma unroll
            for (int j = 0; j < 4; j++)
                load_tile(vbase + (c + 1) * 128 + j * 32, S_LEN, bV + j * 8192, tid);
        }
        asm volatile("cp.async.commit_group;" ::: "memory");
        asm volatile("cp.async.wait_group 1;" ::: "memory");
        __syncthreads();

        const uint32_t bK = sK + (c & 1) * 32768;
        const uint32_t bV = sV + (c & 1) * 32768;

        float sacc[16][4];
#pragma unroll
        for (int t = 0; t < 16; t++)
#pragma unroll
            for (int j = 0; j < 4; j++) sacc[t][j] = 0.f;

#pragma unroll
        for (int kc = 0; kc < 4; kc++) {
#pragma unroll
            for (int ks = 0; ks < 2; ks++) {
                uint32_t AF[4];
                {
                    const int row = wid * 16 + ((quad & 1) << 3) + rr;
                    const int seg = ks * 2 + (quad >> 1);
                    ldm_x4(sQ + kc * 8192 + swz(row, seg), AF);
                }
#pragma unroll
                for (int np = 0; np < 8; np++) {
                    uint32_t BF[4];
                    const int row = np * 16 + ((quad >> 1) << 3) + rr;
                    const int seg = ks * 2 + (quad & 1);
                    ldm_x4(bK + kc * 8192 + swz(row, seg), BF);
                    mma16816(sacc[np * 2],     AF, BF[0], BF[1]);
                    mma16816(sacc[np * 2 + 1], AF, BF[2], BF[3]);
                }
            }
        }

        if (c == qt) {
            const int r0 = wid * 16 + gid, r1 = r0 + 8;
#pragma unroll
            for (int t = 0; t < 16; t++) {
                const int col = t * 8 + tig * 2;
                if (col     > r0) sacc[t][0] = -1e30f;
                if (col + 1 > r0) sacc[t][1] = -1e30f;
                if (col     > r1) sacc[t][2] = -1e30f;
                if (col + 1 > r1) sacc[t][3] = -1e30f;
            }
        }

        float tm0 = -1e30f, tm1 = -1e30f;
#pragma unroll
        for (int t = 0; t < 16; t++) {
            tm0 = fmaxf(tm0, fmaxf(sacc[t][0], sacc[t][1]));
            tm1 = fmaxf(tm1, fmaxf(sacc[t][2], sacc[t][3]));
        }
        tm0 = fmaxf(tm0, __shfl_xor_sync(0xffffffffu, tm0, 1));
        tm0 = fmaxf(tm0, __shfl_xor_sync(0xffffffffu, tm0, 2));
        tm1 = fmaxf(tm1, __shfl_xor_sync(0xffffffffu, tm1, 1));
        tm1 = fmaxf(tm1, __shfl_xor_sync(0xffffffffu, tm1, 2));

        const float mn0 = fmaxf(m0, tm0), mn1 = fmaxf(m1, tm1);
        const float f0 = exp2f((m0 - mn0) * sc2);
        const float f1 = exp2f((m1 - mn1) * sc2);
        m0 = mn0; m1 = mn1;

        float rs0 = 0.f, rs1 = 0.f;
#pragma unroll
        for (int t = 0; t < 16; t++) {
            float p0 = exp2f((sacc[t][0] - mn0) * sc2);
            float p1 = exp2f((sacc[t][1] - mn0) * sc2);
            float p2 = exp2f((sacc[t][2] - mn1) * sc2);
            float p3 = exp2f((sacc[t][3] - mn1) * sc2);
            sacc[t][0] = p0; sacc[t][1] = p1; sacc[t][2] = p2; sacc[t][3] = p3;
            rs0 += p0 + p1; rs1 += p2 + p3;
        }
        rs0 += __shfl_xor_sync(0xffffffffu, rs0, 1);
        rs0 += __shfl_xor_sync(0xffffffffu, rs0, 2);
        rs1 += __shfl_xor_sync(0xffffffffu, rs1, 1);
        rs1 += __shfl_xor_sync(0xffffffffu, rs1, 2);
        l0 = l0 * f0 + rs0;
        l1 = l1 * f1 + rs1;

#pragma unroll
        for (int t = 0; t < 16; t++) {
            oacc[t][0] *= f0; oacc[t][1] *= f0;
            oacc[t][2] *= f1; oacc[t][3] *= f1;
        }

#pragma unroll
        for (int ks = 0; ks < 8; ks++) {
            uint32_t a[4];
            a[0] = packh2(sacc[2 * ks][0],     sacc[2 * ks][1]);
            a[1] = packh2(sacc[2 * ks][2],     sacc[2 * ks][3]);
            a[2] = packh2(sacc[2 * ks + 1][0], sacc[2 * ks + 1][1]);
            a[3] = packh2(sacc[2 * ks + 1][2], sacc[2 * ks + 1][3]);
            const int kc = ks >> 1, ksl = ks & 1;
#pragma unroll
            for (int np = 0; np < 8; np++) {
                uint32_t BF[4];
                const int row = np * 16 + ((quad >> 1) << 3) + rr;
                const int seg = ksl * 2 + (quad & 1);
                ldm_x4(bV + kc * 8192 + swz(row, seg), BF);
                mma16816(oacc[np * 2],     a, BF[0], BF[1]);
                mma16816(oacc[np * 2 + 1], a, BF[2], BF[3]);
            }
        }
        __syncthreads();
    }

    const float i0 = 1.f / l0, i1 = 1.f / l1;
    fp16* obase = o + (size_t)(qt * 128 + wid * 16) * DIM + z * HD;
#pragma unroll
    for (int t = 0; t < 16; t++) {
        const int col = t * 8 + tig * 2;
        __half2 w0, w1;
        w0.x = __float2half(oacc[t][0] * i0); w0.y = __float2half(oacc[t][1] * i0);
        w1.x = __float2half(oacc[t][2] * i1); w1.y = __float2half(oacc[t][3] * i1);
        *(__half2*)(obase + (size_t)gid * DIM + col)       = w0;
        *(__half2*)(obase + (size_t)(gid + 8) * DIM + col) = w1;
    }
}

// ---------------------------------------------------------------------------
// RMSNorm -> fp16
// ---------------------------------------------------------------------------
__global__ void rmsnorm_h_kernel(const float* __restrict__ x, const float* __restrict__ g,
                                 fp16* __restrict__ y) {
    const int row = blockIdx.x;
    const float* xr = x + (size_t)row * DIM;
    float ss = 0.f;
    for (int i = threadIdx.x; i < DIM / 4; i += 256) {
        float4 v = ((const float4*)xr)[i];
        ss += v.x * v.x + v.y * v.y + v.z * v.z + v.w * v.w;
    }
    __shared__ float red[8];
    __shared__ float rr_s;
#pragma unroll
    for (int o = 16; o; o >>= 1) ss += __shfl_xor_sync(0xffffffffu, ss, o);
    if ((threadIdx.x & 31) == 0) red[threadIdx.x >> 5] = ss;
    __syncthreads();
    if (threadIdx.x == 0) {
        float v = 0.f;
#pragma unroll
        for (int i = 0; i < 8; i++) v += red[i];
        rr_s = rsqrtf(v * (1.0f / DIM) + EPS);
    }
    __syncthreads();
    const float rr = rr_s;
    for (int i = threadIdx.x; i < DIM / 4; i += 256) {
        float4 v  = ((const float4*)xr)[i];
        float4 gg = ((const float4*)g)[i];
        __half2 a, b;
        a.x = __float2half(v.x * rr * gg.x);
        a.y = __float2half(v.y * rr * gg.y);
        b.x = __float2half(v.z * rr * gg.z);
        b.y = __float2half(v.w * rr * gg.w);
        const size_t o = (size_t)row * DIM + i * 4;
        *(__half2*)(y + o)     = a;
        *(__half2*)(y + o + 2) = b;
    }
}

// ---------------------------------------------------------------------------
// Weight transpose + convert (proven R9 version): W[K,N] -> WT[N,K] fp16.
// ---------------------------------------------------------------------------
__global__ void wconvT_kernel(const float* __restrict__ W, int K, int N,
                              fp16* __restrict__ T) {
    __shared__ float tb[64][65];
    const int n0 = blockIdx.x * 64, k0 = blockIdx.y * 64;
    const int tx = threadIdx.x, ty = threadIdx.y;   // (32, 8)
#pragma unroll
    for (int r = 0; r < 8; r++) {
        const int row = ty + 8 * r;
        float2 v = *(const float2*)(W + (size_t)(k0 + row) * N + n0 + tx * 2);
        tb[row][tx * 2]     = v.x;
        tb[row][tx * 2 + 1] = v.y;
    }
    __syncthreads();
#pragma unroll
    for (int r = 0; r < 8; r++) {
        const int n = ty + 8 * r;
        __half2 h;
        h.x = __float2half(tb[tx * 2][n]);
        h.y = __float2half(tb[tx * 2 + 1][n]);
        *(__half2*)(T + (size_t)(n0 + n) * K + k0 + tx * 2) = h;
    }
}

// ---------------------------------------------------------------------------
// Orchestration: two side streams for conversions; fused QKV GEMM writes
// roped q/k and transposed V directly (no vconvT kernel).
// ---------------------------------------------------------------------------
extern "C" void kernel_launch(void* const* d_in, const int* in_sizes, int n_in,
                              void* d_out, int out_size) {
    const float* x  = (const float*)d_in[0];
    const float* fc = (const float*)d_in[1];
    const float* fs = (const float*)d_in[2];
    const float* wq = (const float*)d_in[4];
    const float* wk = (const float*)d_in[5];
    const float* wv = (const float*)d_in[6];
    const float* wo = (const float*)d_in[7];
    const float* w1 = (const float*)d_in[8];
    const float* w2 = (const float*)d_in[9];
    const float* w3 = (const float*)d_in[10];
    const float* ga = (const float*)d_in[11];
    const float* gf = (const float*)d_in[12];
    float* out = (float*)d_out;

    cudaFuncSetAttribute(mma_gemm<1>, cudaFuncAttributeMaxDynamicSharedMemorySize, GEMM_SMEM);
    cudaFuncSetAttribute(mma_gemm<3>, cudaFuncAttributeMaxDynamicSharedMemorySize, GEMM_SMEM);
    cudaFuncSetAttribute(ffn_gemm,    cudaFuncAttributeMaxDynamicSharedMemorySize, GEMM_SMEM);
    cudaFuncSetAttribute(flash_kernel, cudaFuncAttributeMaxDynamicSharedMemorySize, FL_SMEM);

    float *h;
    fp16 *xn, *q, *k, *vT, *at, *hn, *u1;
    fp16 *wqkvT, *woT, *w1T, *w2T, *w3T;
    cudaGetSymbolAddress((void**)&h,    g_h);
    cudaGetSymbolAddress((void**)&xn,   g_xn);
    cudaGetSymbolAddress((void**)&q,    g_q);
    cudaGetSymbolAddress((void**)&k,    g_k);
    cudaGetSymbolAddress((void**)&vT,   g_vT);
    cudaGetSymbolAddress((void**)&at,   g_at);
    cudaGetSymbolAddress((void**)&hn,   g_hn);
    cudaGetSymbolAddress((void**)&u1,   g_u1);
    cudaGetSymbolAddress((void**)&wqkvT, g_wqkvT);
    cudaGetSymbolAddress((void**)&woT,  g_woT);
    cudaGetSymbolAddress((void**)&w1T,  g_w1T);
    cudaGetSymbolAddress((void**)&w2T,  g_w2T);
    cudaGetSymbolAddress((void**)&w3T,  g_w3T);

    // one-time host-side stream/event objects
    static cudaStream_t s1 = []() {
        cudaStream_t s; cudaStreamCreateWithFlags(&s, cudaStreamNonBlocking); return s;
    }();
    static cudaStream_t s2 = []() {
        cudaStream_t s; cudaStreamCreateWithFlags(&s, cudaStreamNonBlocking); return s;
    }();
    static cudaEvent_t eFork = []() {
        cudaEvent_t e; cudaEventCreateWithFlags(&e, cudaEventDisableTiming); return e;
    }();
    static cudaEvent_t eQKV1 = []() {
        cudaEvent_t e; cudaEventCreateWithFlags(&e, cudaEventDisableTiming); return e;
    }();
    static cudaEvent_t eQKV2 = []() {
        cudaEvent_t e; cudaEventCreateWithFlags(&e, cudaEventDisableTiming); return e;
    }();
    static cudaEvent_t eWO = []() {
        cudaEvent_t e; cudaEventCreateWithFlags(&e, cudaEventDisableTiming); return e;
    }();
    static cudaEvent_t eFFN1 = []() {
        cudaEvent_t e; cudaEventCreateWithFlags(&e, cudaEventDisableTiming); return e;
    }();
    static cudaEvent_t eFFN2 = []() {
        cudaEvent_t e; cudaEventCreateWithFlags(&e, cudaEventDisableTiming); return e;
    }();
    static cudaEvent_t eW2 = []() {
        cudaEvent_t e; cudaEventCreateWithFlags(&e, cudaEventDisableTiming); return e;
    }();

    const dim3 tb32(32, 8);
    const dim3 g16(16, 16);

    // fork both side streams off the main (capture) stream
    cudaEventRecord(eFork, 0);
    cudaStreamWaitEvent(s1, eFork, 0);
    cudaStreamWaitEvent(s2, eFork, 0);

    // ---- side stream 1: wq, wv, w1, w2 ----
    wconvT_kernel<<<dim3(32, 32), tb32, 0, s1>>>(wq, DIM, DIM, wqkvT);
    wconvT_kernel<<<dim3(32, 32), tb32, 0, s1>>>(wv, DIM, DIM, wqkvT + (size_t)2 * DIM * DIM);
    cudaEventRecord(eQKV1, s1);
    wconvT_kernel<<<dim3(88, 32), tb32, 0, s1>>>(w1, DIM, HIDDEN, w1T);
    cudaEventRecord(eFFN1, s1);
    wconvT_kernel<<<dim3(32, 88), tb32, 0, s1>>>(w2, HIDDEN, DIM, w2T);
    cudaEventRecord(eW2, s1);

    // ---- side stream 2: wk, wo, w3 ----
    wconvT_kernel<<<dim3(32, 32), tb32, 0, s2>>>(wk, DIM, DIM, wqkvT + (size_t)DIM * DIM);
    cudaEventRecord(eQKV2, s2);
    wconvT_kernel<<<dim3(32, 32), tb32, 0, s2>>>(wo, DIM, DIM, woT);
    cudaEventRecord(eWO, s2);
    wconvT_kernel<<<dim3(88, 32), tb32, 0, s2>>>(w3, DIM, HIDDEN, w3T);
    cudaEventRecord(eFFN2, s2);

    // ---- main stream: compute chain ----
    rmsnorm_h_kernel<<<S_LEN, 256>>>(x, ga, xn);

    // fused QKV GEMM (rope q/k + direct-transposed V)
    cudaStreamWaitEvent(0, eQKV1, 0);
    cudaStreamWaitEvent(0, eQKV2, 0);
    mma_gemm<3><<<dim3(QKV_N / 128, 16), 256, GEMM_SMEM>>>(xn, DIM, wqkvT, DIM,
        nullptr, nullptr, q, k, vT, fc, fs, QKV_N, DIM);

    // flash attention
    flash_kernel<<<dim3(16, NHEAD), 256, FL_SMEM>>>(q, k, vT, at);

    // h = x + attn @ wo
    cudaStreamWaitEvent(0, eWO, 0);
    mma_gemm<1><<<g16, 256, GEMM_SMEM>>>(at, DIM, woT, DIM,
        h, x, nullptr, nullptr, nullptr, nullptr, nullptr, DIM, DIM);

    // hn = rmsnorm(h) fp16
    rmsnorm_h_kernel<<<S_LEN, 256>>>(h, gf, hn);

    // fused FFN
    cudaStreamWaitEvent(0, eFFN1, 0);
    cudaStreamWaitEvent(0, eFFN2, 0);
    ffn_gemm<<<dim3(HIDDEN / 64, 16), 256, GEMM_SMEM>>>(hn, DIM, w1T, w3T, DIM,
        u1, HIDDEN, DIM);

    // out = h + u1 @ w2 (joins s1 branch)
    cudaStreamWaitEvent(0, eW2, 0);
    mma_gemm<1><<<g16, 256, GEMM_SMEM>>>(u1, HIDDEN, w2T, HIDDEN,
        out, h, nullptr, nullptr, nullptr, nullptr, nullptr, DIM, HIDDEN);
}

// round 15
// speedup vs baseline: 1.0195x; 1.0027x over previous
#include <cuda_runtime.h>
#include <cuda_fp16.h>
#include <math.h>
#include <stdint.h>

#define S_LEN   2048
#define DIM     2048
#define NHEAD   16
#define HD      128
#define HIDDEN  5632
#define EPS     1e-6f
#define QKV_N   (3 * DIM)     // 6144

using fp16 = __half;

// ---------------------------------------------------------------------------
// Device scratch
// ---------------------------------------------------------------------------
__device__ float g_h  [S_LEN * DIM];

__device__ fp16 g_xn [S_LEN * DIM];
__device__ fp16 g_q  [S_LEN * DIM];
__device__ fp16 g_k  [S_LEN * DIM];
__device__ fp16 g_vT [NHEAD * HD * S_LEN];
__device__ fp16 g_at [S_LEN * DIM];
__device__ fp16 g_hn [S_LEN * DIM];
__device__ fp16 g_u1 [(size_t)S_LEN * HIDDEN];

__device__ fp16 g_wqkvT[(size_t)QKV_N * DIM];              // [6144, 2048]
__device__ fp16 g_woT[DIM * DIM];
__device__ fp16 g_w1T[(size_t)HIDDEN * DIM];
__device__ fp16 g_w3T[(size_t)HIDDEN * DIM];
__device__ fp16 g_w2T[(size_t)DIM * HIDDEN];

// ---------------------------------------------------------------------------
// Helpers
// ---------------------------------------------------------------------------
__device__ __forceinline__ uint32_t smem_u32(const void* p) {
    uint32_t a;
    asm("{ .reg .u64 t; cvta.to.shared.u64 t, %1; cvt.u32.u64 %0, t; }" : "=r"(a) : "l"(p));
    return a;
}
__device__ __forceinline__ void cpa16(uint32_t d, const void* g) {
    asm volatile("cp.async.cg.shared.global [%0], [%1], 16;" :: "r"(d), "l"(g));
}
__device__ __forceinline__ void ldm_x4(uint32_t a, uint32_t (&f)[4]) {
    asm volatile("ldmatrix.sync.aligned.m8n8.x4.shared.b16 {%0,%1,%2,%3}, [%4];"
                 : "=r"(f[0]), "=r"(f[1]), "=r"(f[2]), "=r"(f[3]) : "r"(a));
}
__device__ __forceinline__ void mma16816(float (&c)[4], const uint32_t (&a)[4],
                                         uint32_t b0, uint32_t b1) {
    asm volatile("mma.sync.aligned.m16n8k16.row.col.f32.f16.f16.f32 "
                 "{%0,%1,%2,%3}, {%4,%5,%6,%7}, {%8,%9}, {%0,%1,%2,%3};"
                 : "+f"(c[0]), "+f"(c[1]), "+f"(c[2]), "+f"(c[3])
                 : "r"(a[0]), "r"(a[1]), "r"(a[2]), "r"(a[3]), "r"(b0), "r"(b1));
}
__device__ __forceinline__ uint32_t packh2(float lo, float hi) {
    uint32_t r;
    asm("cvt.rn.f16x2.f32 %0, %1, %2;" : "=r"(r) : "f"(hi), "f"(lo));
    return r;
}

// swizzled byte offset within a Rx32-fp16 tile (64B rows, 16B segs)
__device__ __forceinline__ uint32_t swz(int row, int seg) {
    return (uint32_t)(row * 64 + ((seg ^ ((row >> 1) & 3)) << 4));
}

// stage a 128x32 fp16 tile smem<-gmem via cp.async (256 threads, 2 ops/thread)
__device__ __forceinline__ void load_tile(const fp16* __restrict__ src, int ld,
                                          uint32_t dst, int tid) {
#pragma unroll
    for (int i = 0; i < 2; i++) {
        const int s = tid + i * 256;
        const int row = s >> 2, seg = s & 3;
        cpa16(dst + swz(row, seg), src + (size_t)row * ld + seg * 8);
    }
}
// stage a 64x32 fp16 tile (1 op/thread)
__device__ __forceinline__ void load_tile64(const fp16* __restrict__ src, int ld,
                                            uint32_t dst, int tid) {
    const int row = tid >> 2, seg = tid & 3;
    cpa16(dst + swz(row, seg), src + (size_t)row * ld + seg * 8);
}

// ---------------------------------------------------------------------------
// mma_gemm (dense GEMMs): C[M,N] = A[M,K] @ B[N,K]^T, fp16 in, fp32 accum.
// EPI: 1 fp32 + Dx residual; 3 QKV mode (rope q/k fp16 + V direct-transposed)
// 128x128 tile, 8 warps (2x4), warp 64x32, K-chunk 32, 3-stage cp.async.
// ---------------------------------------------------------------------------
#define NSTAGE 3
#define GEMM_SMEM (NSTAGE * 16384)

template<int EPI>
__global__ __launch_bounds__(256)
void mma_gemm(const fp16* __restrict__ A_, int lda,
              const fp16* __restrict__ B_, int ldb,
              float* __restrict__ Cf, const float* __restrict__ Dx,
              fp16* __restrict__ Cq, fp16* __restrict__ Ck, fp16* __restrict__ CvT,
              const float* __restrict__ fc, const float* __restrict__ fs,
              int ldc, int K)
{
    const int m0 = blockIdx.y * 128, n0 = blockIdx.x * 128;
    const int nc = K >> 5;

    extern __shared__ char smem[];
    const uint32_t sb = smem_u32(smem);
    const int tid = threadIdx.x, wid = tid >> 5, lid = tid & 31;
    const int wm = wid >> 2, wn = wid & 3;

    const fp16* pA = A_ + (size_t)m0 * lda;
    const fp16* pB = B_ + (size_t)n0 * ldb;

    float acc[4][4][4];
#pragma unroll
    for (int i = 0; i < 4; i++)
#pragma unroll
        for (int j = 0; j < 4; j++)
#pragma unroll
            for (int t = 0; t < 4; t++) acc[i][j][t] = 0.f;

#pragma unroll
    for (int s = 0; s < NSTAGE - 1; s++) {
        if (s < nc) {
            const uint32_t base = sb + s * 16384;
            load_tile(pA + s * 32, lda, base,        tid);
            load_tile(pB + s * 32, ldb, base + 8192, tid);
        }
        asm volatile("cp.async.commit_group;" ::: "memory");
    }

    const int quad = lid >> 3, rr = lid & 7;

    for (int c = 0; c < nc; c++) {
        const int cp = c + NSTAGE - 1;
        if (cp < nc) {
            const uint32_t base = sb + (cp % NSTAGE) * 16384;
            load_tile(pA + cp * 32, lda, base,        tid);
            load_tile(pB + cp * 32, ldb, base + 8192, tid);
        }
        asm volatile("cp.async.commit_group;" ::: "memory");
        asm volatile("cp.async.wait_group %0;" :: "n"(NSTAGE - 1) : "memory");
        __syncthreads();

        const uint32_t base = sb + (c % NSTAGE) * 16384;
#pragma unroll
        for (int ks = 0; ks < 2; ks++) {
            uint32_t AF[4][4], BF[2][4];
#pragma unroll
            for (int mi = 0; mi < 4; mi++) {
                const int row = wm * 64 + mi * 16 + ((quad & 1) << 3) + rr;
                const int seg = ks * 2 + (quad >> 1);
                ldm_x4(base + swz(row, seg), AF[mi]);
            }
#pragma unroll
            for (int nj = 0; nj < 2; nj++) {
                const int row = wn * 32 + nj * 16 + ((quad >> 1) << 3) + rr;
                const int seg = ks * 2 + (quad & 1);
                ldm_x4(base + 8192 + swz(row, seg), BF[nj]);
            }
#pragma unroll
            for (int mi = 0; mi < 4; mi++)
#pragma unroll
                for (int nj = 0; nj < 2; nj++) {
                    mma16816(acc[mi][nj * 2],     AF[mi], BF[nj][0], BF[nj][1]);
                    mma16816(acc[mi][nj * 2 + 1], AF[mi], BF[nj][2], BF[nj][3]);
                }
        }
        __syncthreads();
    }

    const int gid = lid >> 2, tig = lid & 3;

#pragma unroll
    for (int mi = 0; mi < 4; mi++) {
#pragma unroll
        for (int k4 = 0; k4 < 4; k4++) {
            const int col = n0 + wn * 32 + k4 * 8 + tig * 2;
#pragma unroll
            for (int h2 = 0; h2 < 2; h2++) {
                const int row = m0 + wm * 64 + mi * 16 + gid + h2 * 8;
                float v0 = acc[mi][k4][h2 * 2 + 0];
                float v1 = acc[mi][k4][h2 * 2 + 1];
                if (EPI == 1) {
                    const size_t off = (size_t)row * ldc + col;
                    float2 d = *(const float2*)(Dx + off);
                    *(float2*)(Cf + off) = make_float2(v0 + d.x, v1 + d.y);
                } else {
                    // EPI == 3: QKV mode. col in [0, 6144).
                    if (col < 4096) {
                        const int i = (col & 127) >> 1;
                        const float co = fc[row * 64 + i];
                        const float si = fs[row * 64 + i];
                        const float r_ = v0 * co - v1 * si;
                        const float i_ = v0 * si + v1 * co;
                        fp16* dst = (col < 2048) ? Cq : Ck;
                        __half2 t;
                        t.x = __float2half(r_); t.y = __float2half(i_);
                        *(__half2*)(dst + (size_t)row * DIM + (col & 2047)) = t;
                    } else {
                        // V: write directly transposed vT[h][d][t]
                        const int c2 = col - 4096;     // head h = c2>>7, d = c2&127
                        fp16* dst = CvT + (size_t)c2 * S_LEN + row;
                        dst[0]     = __float2half(v0);
                        dst[S_LEN] = __float2half(v1);
                    }
                }
            }
        }
    }
}

// ---------------------------------------------------------------------------
// ffn_gemm: u1 = silu(hn @ w1) * (hn @ w3), fp16 out.
// ---------------------------------------------------------------------------
__global__ __launch_bounds__(256)
void ffn_gemm(const fp16* __restrict__ A_, int lda,
              const fp16* __restrict__ B1_, const fp16* __restrict__ B3_, int ldb,
              fp16* __restrict__ U, int ldu, int K)
{
    const int m0 = blockIdx.y * 128, n0 = blockIdx.x * 64;
    const int nc = K >> 5;

    extern __shared__ char smem[];
    const uint32_t sb = smem_u32(smem);
    const int tid = threadIdx.x, wid = tid >> 5, lid = tid & 31;
    const int wm = wid >> 2, wn = wid & 3;

    const fp16* pA  = A_  + (size_t)m0 * lda;
    const fp16* pB1 = B1_ + (size_t)n0 * ldb;
    const fp16* pB3 = B3_ + (size_t)n0 * ldb;

    float acc[4][4][4];
#pragma unroll
    for (int i = 0; i < 4; i++)
#pragma unroll
        for (int j = 0; j < 4; j++)
#pragma unroll
            for (int t = 0; t < 4; t++) acc[i][j][t] = 0.f;

#pragma unroll
    for (int s = 0; s < NSTAGE - 1; s++) {
        if (s < nc) {
            const uint32_t base = sb + s * 16384;
            load_tile  (pA  + s * 32, lda, base,         tid);
            load_tile64(pB1 + s * 32, ldb, base + 8192,  tid);
            load_tile64(pB3 + s * 32, ldb, base + 12288, tid);
        }
        asm volatile("cp.async.commit_group;" ::: "memory");
    }

    const int quad = lid >> 3, rr = lid & 7;

    for (int c = 0; c < nc; c++) {
        const int cp = c + NSTAGE - 1;
        if (cp < nc) {
            const uint32_t base = sb + (cp % NSTAGE) * 16384;
            load_tile  (pA  + cp * 32, lda, base,         tid);
            load_tile64(pB1 + cp * 32, ldb, base + 8192,  tid);
            load_tile64(pB3 + cp * 32, ldb, base + 12288, tid);
        }
        asm volatile("cp.async.commit_group;" ::: "memory");
        asm volatile("cp.async.wait_group %0;" :: "n"(NSTAGE - 1) : "memory");
        __syncthreads();

        const uint32_t base = sb + (c % NSTAGE) * 16384;
        const uint32_t bB = base + ((wn < 2) ? 8192 : 12288);
#pragma unroll
        for (int ks = 0; ks < 2; ks++) {
            uint32_t AF[4][4], BF[2][4];
#pragma unroll
            for (int mi = 0; mi < 4; mi++) {
                const int row = wm * 64 + mi * 16 + ((quad & 1) << 3) + rr;
                const int seg = ks * 2 + (quad >> 1);
                ldm_x4(base + swz(row, seg), AF[mi]);
            }
#pragma unroll
            for (int nj = 0; nj < 2; nj++) {
                const int row = (wn & 1) * 32 + nj * 16 + ((quad >> 1) << 3) + rr;
                const int seg = ks * 2 + (quad & 1);
                ldm_x4(bB + swz(row, seg), BF[nj]);
            }
#pragma unroll
            for (int mi = 0; mi < 4; mi++)
#pragma unroll
                for (int nj = 0; nj < 2; nj++) {
                    mma16816(acc[mi][nj * 2],     AF[mi], BF[nj][0], BF[nj][1]);
                    mma16816(acc[mi][nj * 2 + 1], AF[mi], BF[nj][2], BF[nj][3]);
                }
        }
        __syncthreads();
    }

    float* stg = (float*)smem;    // 128 x 64 fp32 = 32KB
    const int gid = lid >> 2, tig = lid & 3;

    if (wn >= 2) {
#pragma unroll
        for (int mi = 0; mi < 4; mi++)
#pragma unroll
            for (int k4 = 0; k4 < 4; k4++) {
                const int col = (wn & 1) * 32 + k4 * 8 + tig * 2;
#pragma unroll
                for (int h2 = 0; h2 < 2; h2++) {
                    const int row = wm * 64 + mi * 16 + gid + h2 * 8;
                    *(float2*)(stg + row * 64 + col) =
                        make_float2(acc[mi][k4][h2 * 2], acc[mi][k4][h2 * 2 + 1]);
                }
            }
    }
    __syncthreads();
    if (wn < 2) {
#pragma unroll
        for (int mi = 0; mi < 4; mi++)
#pragma unroll
            for (int k4 = 0; k4 < 4; k4++) {
                const int col = (wn & 1) * 32 + k4 * 8 + tig * 2;
#pragma unroll
                for (int h2 = 0; h2 < 2; h2++) {
                    const int row = wm * 64 + mi * 16 + gid + h2 * 8;
                    float a0 = acc[mi][k4][h2 * 2], a1 = acc[mi][k4][h2 * 2 + 1];
                    float2 d = *(const float2*)(stg + row * 64 + col);
                    float u0 = a0 / (1.f + expf(-a0)) * d.x;
                    float u1v = a1 / (1.f + expf(-a1)) * d.y;
                    __half2 t;
                    t.x = __float2half(u0); t.y = __float2half(u1v);
                    *(__half2*)(U + (size_t)(m0 + row) * ldu + n0 + col) = t;
                }
            }
    }
}

// ---------------------------------------------------------------------------
// Flash attention (unchanged)
// ---------------------------------------------------------------------------
#define FL_SMEM (32768 + 65536 + 65536)

__global__ __launch_bounds__(256, 1)
void flash_kernel(const fp16* __restrict__ q, const fp16* __restrict__ k,
                  const fp16* __restrict__ vT, fp16* __restrict__ o)
{
    const int qt = 15 - blockIdx.x;
    const int z  = blockIdx.y;
    const int nkv = qt + 1;

    extern __shared__ char smem[];
    const uint32_t sQ = smem_u32(smem);
    const uint32_t sK = sQ + 32768;
    const uint32_t sV = sQ + 98304;

    const int tid = threadIdx.x, wid = tid >> 5, lid = tid & 31;
    const int gid = lid >> 2, tig = lid & 3;
    const int quad = lid >> 3, rr = lid & 7;

    const fp16* qbase = q + (size_t)(qt * 128) * DIM + z * HD;
    const fp16* kbase = k + z * HD;
    const fp16* vbase = vT + (size_t)z * HD * S_LEN;

#pragma unroll
    for (int j = 0; j < 4; j++) load_tile(qbase + j * 32, DIM, sQ + j * 8192, tid);
#pragma unroll
    for (int j = 0; j < 4; j++) load_tile(kbase + j * 32, DIM, sK + j * 8192, tid);
#pragma unroll
    for (int j = 0; j < 4; j++) load_tile(vbase + j * 32, S_LEN, sV + j * 8192, tid);
    asm volatile("cp.async.commit_group;" ::: "memory");

    float oacc[16][4];
#pragma unroll
    for (int t = 0; t < 16; t++)
#pragma unroll
        for (int j = 0; j < 4; j++) oacc[t][j] = 0.f;
    float m0 = -1e30f, m1 = -1e30f, l0 = 0.f, l1 = 0.f;
    const float sc2 = 0.08838834764831845f * 1.4426950408889634f;

    for (int c = 0; c < nkv; c++) {
        if (c + 1 < nkv) {
            const uint32_t bK = sK + ((c + 1) & 1) * 32768;
            const uint32_t bV = sV + ((c + 1) & 1) * 32768;
#pragma unroll
            for (int j = 0; j < 4; j++)
                load_tile(kbase + (size_t)((c + 1) * 128) * DIM + j * 32, DIM, bK + j * 8192, tid);
#pragma unroll
            for (int j = 0; j < 4; j++)
                load_tile(vbase + (c + 1) * 128 + j * 32, S_LEN, bV + j * 8192, tid);
        }
        asm volatile("cp.async.commit_group;" ::: "memory");
        asm volatile("cp.async.wait_group 1;" ::: "memory");
        __syncthreads();

        const uint32_t bK = sK + (c & 1) * 32768;
        const uint32_t bV = sV + (c & 1) * 32768;

        float sacc[16][4];
#pragma unroll
        for (int t = 0; t < 16; t++)
#pragma unroll
            for (int j = 0; j < 4; j++) sacc[t][j] = 0.f;

#pragma unroll
        for (int kc = 0; kc < 4; kc++) {
#pragma unroll
            for (int ks = 0; ks < 2; ks++) {
                uint32_t AF[4];
                {
                    const int row = wid * 16 + ((quad & 1) << 3) + rr;
                    const int seg = ks * 2 + (quad >> 1);
                    ldm_x4(sQ + kc * 8192 + swz(row, seg), AF);
                }
#pragma unroll
                for (int np = 0; np < 8; np++) {
                    uint32_t BF[4];
                    const int row = np * 16 + ((quad >> 1) << 3) + rr;
                    const int seg = ks * 2 + (quad & 1);
                    ldm_x4(bK + kc * 8192 + swz(row, seg), BF);
                    mma16816(sacc[np * 2],     AF, BF[0], BF[1]);
                    mma16816(sacc[np * 2 + 1], AF, BF[2], BF[3]);
                }
            }
        }

        if (c == qt) {
            const int r0 = wid * 16 + gid, r1 = r0 + 8;
#pragma unroll
            for (int t = 0; t < 16; t++) {
                const int col = t * 8 + tig * 2;
                if (col     > r0) sacc[t][0] = -1e30f;
                if (col + 1 > r0) sacc[t][1] = -1e30f;
                if (col     > r1) sacc[t][2] = -1e30f;
                if (col + 1 > r1) sacc[t][3] = -1e30f;
            }
        }

        float tm0 = -1e30f, tm1 = -1e30f;
#pragma unroll
        for (int t = 0; t < 16; t++) {
            tm0 = fmaxf(tm0, fmaxf(sacc[t][0], sacc[t][1]));
            tm1 = fmaxf(tm1, fmaxf(sacc[t][2], sacc[t][3]));
        }
        tm0 = fmaxf(tm0, __shfl_xor_sync(0xffffffffu, tm0, 1));
        tm0 = fmaxf(tm0, __shfl_xor_sync(0xffffffffu, tm0, 2));
        tm1 = fmaxf(tm1, __shfl_xor_sync(0xffffffffu, tm1, 1));
        tm1 = fmaxf(tm1, __shfl_xor_sync(0xffffffffu, tm1, 2));

        const float mn0 = fmaxf(m0, tm0), mn1 = fmaxf(m1, tm1);
        const float f0 = exp2f((m0 - mn0) * sc2);
        const float f1 = exp2f((m1 - mn1) * sc2);
        m0 = mn0; m1 = mn1;

        float rs0 = 0.f, rs1 = 0.f;
#pragma unroll
        for (int t = 0; t < 16; t++) {
            float p0 = exp2f((sacc[t][0] - mn0) * sc2);
            float p1 = exp2f((sacc[t][1] - mn0) * sc2);
            float p2 = exp2f((sacc[t][2] - mn1) * sc2);
            float p3 = exp2f((sacc[t][3] - mn1) * sc2);
            sacc[t][0] = p0; sacc[t][1] = p1; sacc[t][2] = p2; sacc[t][3] = p3;
            rs0 += p0 + p1; rs1 += p2 + p3;
        }
        rs0 += __shfl_xor_sync(0xffffffffu, rs0, 1);
        rs0 += __shfl_xor_sync(0xffffffffu, rs0, 2);
        rs1 += __shfl_xor_sync(0xffffffffu, rs1, 1);
        rs1 += __shfl_xor_sync(0xffffffffu, rs1, 2);
        l0 = l0 * f0 + rs0;
        l1 = l1 * f1 + rs1;

#pragma unroll
        for (int t = 0; t < 16; t++) {
            oacc[t][0] *= f0; oacc[t][1] *= f0;
            oacc[t][2] *= f1; oacc[t][3] *= f1;
        }

#pragma unroll
        for (int ks = 0; ks < 8; ks++) {
            uint32_t a[4];
            a[0] = packh2(sacc[2 * ks][0],     sacc[2 * ks][1]);
            a[1] = packh2(sacc[2 * ks][2],     sacc[2 * ks][3]);
            a[2] = packh2(sacc[2 * ks + 1][0], sacc[2 * ks + 1][1]);
            a[3] = packh2(sacc[2 * ks + 1][2], sacc[2 * ks + 1][3]);
            const int kc = ks >> 1, ksl = ks & 1;
#pragma unroll
            for (int np = 0; np < 8; np++) {
                uint32_t BF[4];
                const int row = np * 16 + ((quad >> 1) << 3) + rr;
                const int seg = ksl * 2 + (quad & 1);
                ldm_x4(bV + kc * 8192 + swz(row, seg), BF);
                mma16816(oacc[np * 2],     a, BF[0], BF[1]);
                mma16816(oacc[np * 2 + 1], a, BF[2], BF[3]);
            }
        }
        __syncthreads();
    }

    const float i0 = 1.f / l0, i1 = 1.f / l1;
    fp16* obase = o + (size_t)(qt * 128 + wid * 16) * DIM + z * HD;
#pragma unroll
    for (int t = 0; t < 16; t++) {
        const int col = t * 8 + tig * 2;
        __half2 w0, w1;
        w0.x = __float2half(oacc[t][0] * i0); w0.y = __float2half(oacc[t][1] * i0);
        w1.x = __float2half(oacc[t][2] * i1); w1.y = __float2half(oacc[t][3] * i1);
        *(__half2*)(obase + (size_t)gid * DIM + col)       = w0;
        *(__half2*)(obase + (size_t)(gid + 8) * DIM + col) = w1;
    }
}

// ---------------------------------------------------------------------------
// RMSNorm -> fp16
// ---------------------------------------------------------------------------
__global__ void rmsnorm_h_kernel(const float* __restrict__ x, const float* __restrict__ g,
                                 fp16* __restrict__ y) {
    const int row = blockIdx.x;
    const float* xr = x + (size_t)row * DIM;
    float ss = 0.f;
    for (int i = threadIdx.x; i < DIM / 4; i += 256) {
        float4 v = ((const float4*)xr)[i];
        ss += v.x * v.x + v.y * v.y + v.z * v.z + v.w * v.w;
    }
    __shared__ float red[8];
    __shared__ float rr_s;
#pragma unroll
    for (int o = 16; o; o >>= 1) ss += __shfl_xor_sync(0xffffffffu, ss, o);
    if ((threadIdx.x & 31) == 0) red[threadIdx.x >> 5] = ss;
    __syncthreads();
    if (threadIdx.x == 0) {
        float v = 0.f;
#pragma unroll
        for (int i = 0; i < 8; i++) v += red[i];
        rr_s = rsqrtf(v * (1.0f / DIM) + EPS);
    }
    __syncthreads();
    const float rr = rr_s;
    for (int i = threadIdx.x; i < DIM / 4; i += 256) {
        float4 v  = ((const float4*)xr)[i];
        float4 gg = ((const float4*)g)[i];
        __half2 a, b;
        a.x = __float2half(v.x * rr * gg.x);
        a.y = __float2half(v.y * rr * gg.y);
        b.x = __float2half(v.z * rr * gg.z);
        b.y = __float2half(v.w * rr * gg.w);
        const size_t o = (size_t)row * DIM + i * 4;
        *(__half2*)(y + o)     = a;
        *(__half2*)(y + o + 2) = b;
    }
}

// ---------------------------------------------------------------------------
// Weight transpose + convert (proven R9 version): W[K,N] -> WT[N,K] fp16.
// ---------------------------------------------------------------------------
__global__ void wconvT_kernel(const float* __restrict__ W, int K, int N,
                              fp16* __restrict__ T) {
    __shared__ float tb[64][65];
    const int n0 = blockIdx.x * 64, k0 = blockIdx.y * 64;
    const int tx = threadIdx.x, ty = threadIdx.y;   // (32, 8)
#pragma unroll
    for (int r = 0; r < 8; r++) {
        const int row = ty + 8 * r;
        float2 v = *(const float2*)(W + (size_t)(k0 + row) * N + n0 + tx * 2);
        tb[row][tx * 2]     = v.x;
        tb[row][tx * 2 + 1] = v.y;
    }
    __syncthreads();
#pragma unroll
    for (int r = 0; r < 8; r++) {
        const int n = ty + 8 * r;
        __half2 h;
        h.x = __float2half(tb[tx * 2][n]);
        h.y = __float2half(tb[tx * 2 + 1][n]);
        *(__half2*)(T + (size_t)(n0 + n) * K + k0 + tx * 2) = h;
    }
}

// ---------------------------------------------------------------------------
// Orchestration: two side streams for conversions; fused QKV GEMM writes
// roped q/k and transposed V directly (no vconvT kernel).
// ---------------------------------------------------------------------------
extern "C" void kernel_launch(void* const* d_in, const int* in_sizes, int n_in,
                              void* d_out, int out_size) {
    const float* x  = (const float*)d_in[0];
    const float* fc = (const float*)d_in[1];
    const float* fs = (const float*)d_in[2];
    const float* wq = (const float*)d_in[4];
    const float* wk = (const float*)d_in[5];
    const float* wv = (const float*)d_in[6];
    const float* wo = (const float*)d_in[7];
    const float* w1 = (const float*)d_in[8];
    const float* w2 = (const float*)d_in[9];
    const float* w3 = (const float*)d_in[10];
    const float* ga = (const float*)d_in[11];
    const float* gf = (const float*)d_in[12];
    float* out = (float*)d_out;

    cudaFuncSetAttribute(mma_gemm<1>, cudaFuncAttributeMaxDynamicSharedMemorySize, GEMM_SMEM);
    cudaFuncSetAttribute(mma_gemm<3>, cudaFuncAttributeMaxDynamicSharedMemorySize, GEMM_SMEM);
    cudaFuncSetAttribute(ffn_gemm,    cudaFuncAttributeMaxDynamicSharedMemorySize, GEMM_SMEM);
    cudaFuncSetAttribute(flash_kernel, cudaFuncAttributeMaxDynamicSharedMemorySize, FL_SMEM);

    float *h;
    fp16 *xn, *q, *k, *vT, *at, *hn, *u1;
    fp16 *wqkvT, *woT, *w1T, *w2T, *w3T;
    cudaGetSymbolAddress((void**)&h,    g_h);
    cudaGetSymbolAddress((void**)&xn,   g_xn);
    cudaGetSymbolAddress((void**)&q,    g_q);
    cudaGetSymbolAddress((void**)&k,    g_k);
    cudaGetSymbolAddress((void**)&vT,   g_vT);
    cudaGetSymbolAddress((void**)&at,   g_at);
    cudaGetSymbolAddress((void**)&hn,   g_hn);
    cudaGetSymbolAddress((void**)&u1,   g_u1);
    cudaGetSymbolAddress((void**)&wqkvT, g_wqkvT);
    cudaGetSymbolAddress((void**)&woT,  g_woT);
    cudaGetSymbolAddress((void**)&w1T,  g_w1T);
    cudaGetSymbolAddress((void**)&w2T,  g_w2T);
    cudaGetSymbolAddress((void**)&w3T,  g_w3T);

    // one-time host-side stream/event objects
    static cudaStream_t s1 = []() {
        cudaStream_t s; cudaStreamCreateWithFlags(&s, cudaStreamNonBlocking); return s;
    }();
    static cudaStream_t s2 = []() {
        cudaStream_t s; cudaStreamCreateWithFlags(&s, cudaStreamNonBlocking); return s;
    }();
    static cudaEvent_t eFork = []() {
        cudaEvent_t e; cudaEventCreateWithFlags(&e, cudaEventDisableTiming); return e;
    }();
    static cudaEvent_t eQKV1 = []() {
        cudaEvent_t e; cudaEventCreateWithFlags(&e, cudaEventDisableTiming); return e;
    }();
    static cudaEvent_t eQKV2 = []() {
        cudaEvent_t e; cudaEventCreateWithFlags(&e, cudaEventDisableTiming); return e;
    }();
    static cudaEvent_t eWO = []() {
        cudaEvent_t e; cudaEventCreateWithFlags(&e, cudaEventDisableTiming); return e;
    }();
    static cudaEvent_t eFFN1 = []() {
        cudaEvent_t e; cudaEventCreateWithFlags(&e, cudaEventDisableTiming); return e;
    }();
    static cudaEvent_t eFFN2 = []() {
        cudaEvent_t e; cudaEventCreateWithFlags(&e, cudaEventDisableTiming); return e;
    }();
    static cudaEvent_t eW2 = []() {
        cudaEvent_t e; cudaEventCreateWithFlags(&e, cudaEventDisableTiming); return e;
    }();

    const dim3 tb32(32, 8);
    const dim3 g16(16, 16);

    // fork both side streams off the main (capture) stream
    cudaEventRecord(eFork, 0);
    cudaStreamWaitEvent(s1, eFork, 0);
    cudaStreamWaitEvent(s2, eFork, 0);

    // ---- side stream 1: wq, wv, w1, w2 ----
    wconvT_kernel<<<dim3(32, 32), tb32, 0, s1>>>(wq, DIM, DIM, wqkvT);
    wconvT_kernel<<<dim3(32, 32), tb32, 0, s1>>>(wv, DIM, DIM, wqkvT + (size_t)2 * DIM * DIM);
    cudaEventRecord(eQKV1, s1);
    wconvT_kernel<<<dim3(88, 32), tb32, 0, s1>>>(w1, DIM, HIDDEN, w1T);
    cudaEventRecord(eFFN1, s1);
    wconvT_kernel<<<dim3(32, 88), tb32, 0, s1>>>(w2, HIDDEN, DIM, w2T);
    cudaEventRecord(eW2, s1);

    // ---- side stream 2: wk, wo, w3 ----
    wconvT_kernel<<<dim3(32, 32), tb32, 0, s2>>>(wk, DIM, DIM, wqkvT + (size_t)DIM * DIM);
    cudaEventRecord(eQKV2, s2);
    wconvT_kernel<<<dim3(32, 32), tb32, 0, s2>>>(wo, DIM, DIM, woT);
    cudaEventRecord(eWO, s2);
    wconvT_kernel<<<dim3(88, 32), tb32, 0, s2>>>(w3, DIM, HIDDEN, w3T);
    cudaEventRecord(eFFN2, s2);

    // ---- main stream: compute chain ----
    rmsnorm_h_kernel<<<S_LEN, 256>>>(x, ga, xn);

    // fused QKV GEMM (rope q/k + direct-transposed V)
    cudaStreamWaitEvent(0, eQKV1, 0);
    cudaStreamWaitEvent(0, eQKV2, 0);
    mma_gemm<3><<<dim3(QKV_N / 128, 16), 256, GEMM_SMEM>>>(xn, DIM, wqkvT, DIM,
        nullptr, nullptr, q, k, vT, fc, fs, QKV_N, DIM);

    // flash attention
    flash_kernel<<<dim3(16, NHEAD), 256, FL_SMEM>>>(q, k, vT, at);

    // h = x + attn @ wo
    cudaStreamWaitEvent(0, eWO, 0);
    mma_gemm<1><<<g16, 256, GEMM_SMEM>>>(at, DIM, woT, DIM,
        h, x, nullptr, nullptr, nullptr, nullptr, nullptr, DIM, DIM);

    // hn = rmsnorm(h) fp16
    rmsnorm_h_kernel<<<S_LEN, 256>>>(h, gf, hn);

    // fused FFN
    cudaStreamWaitEvent(0, eFFN1, 0);
    cudaStreamWaitEvent(0, eFFN2, 0);
    ffn_gemm<<<dim3(HIDDEN / 64, 16), 256, GEMM_SMEM>>>(hn, DIM, w1T, w3T, DIM,
        u1, HIDDEN, DIM);

    // out = h + u1 @ w2 (joins s1 branch)
    cudaStreamWaitEvent(0, eW2, 0);
    mma_gemm<1><<<g16, 256, GEMM_SMEM>>>(u1, HIDDEN, w2T, HIDDEN,
        out, h, nullptr, nullptr, nullptr, nullptr, nullptr, DIM, HIDDEN);
}